// round 1
// baseline (speedup 1.0000x reference)
#include <cuda_runtime.h>
#include <math.h>

// Problem constants (fixed by the dataset)
#define BATCH   8
#define HW      128          // H = W = 128
#define LTOK    16384        // H*W
#define C       192
#define WS      8
#define SHIFT   4
#define NH      6
#define HD      32
#define NWIN    2048         // BATCH * 16 * 16
#define NTOK    131072       // NWIN * 64
#define NWTOK   64           // ws*ws

// ---------------- scratch (device globals; no cudaMalloc allowed) ----------
__device__ float g_xw  [(size_t)NTOK * C];        // LN1'd, shifted, windowed
__device__ float g_qkv [(size_t)NTOK * 3 * C];    // qkv
__device__ float g_attn[(size_t)NTOK * C];        // attention output (window order)
__device__ float g_x1  [(size_t)NTOK * C];        // shortcut + proj (token order)
__device__ float g_xn2 [(size_t)NTOK * C];        // LN2 output
__device__ float g_h1  [(size_t)NTOK * 4 * C];    // MLP hidden

// window-row (w*64+n) -> flat token index (b*16384 + h*128 + w), accounting for
// the -shift roll (and its inverse on the way back: same bijection)
__device__ __forceinline__ int win_row_to_tok(int row) {
    int w  = row >> 6;
    int n  = row & 63;
    int b  = w >> 8;
    int wy = (w >> 4) & 15;
    int wx = w & 15;
    int iy = n >> 3;
    int ix = n & 7;
    int hr = (wy * WS + iy + SHIFT) & (HW - 1);
    int wr = (wx * WS + ix + SHIFT) & (HW - 1);
    return (b << 14) + (hr << 7) + wr;
}

// ---------------- LayerNorm (one warp per token) ---------------------------
// GATHER=true: read x at shifted/windowed source position, write window order.
// GATHER=false: read/write token order.
template<bool GATHER>
__global__ __launch_bounds__(256) void ln_kernel(const float* __restrict__ x,
                                                 const float* __restrict__ s,
                                                 const float* __restrict__ b,
                                                 float* __restrict__ out) {
    int warp = threadIdx.x >> 5;
    int lane = threadIdx.x & 31;
    int row  = blockIdx.x * 8 + warp;   // < NTOK
    int src  = GATHER ? win_row_to_tok(row) : row;
    const float* xp = x + (size_t)src * C;

    float v[6];
    float sum = 0.f, sq = 0.f;
#pragma unroll
    for (int i = 0; i < 6; i++) {
        v[i] = xp[lane + i * 32];
        sum += v[i];
        sq  += v[i] * v[i];
    }
#pragma unroll
    for (int o = 16; o > 0; o >>= 1) {
        sum += __shfl_xor_sync(0xffffffffu, sum, o);
        sq  += __shfl_xor_sync(0xffffffffu, sq, o);
    }
    float mean = sum * (1.f / C);
    float var  = sq * (1.f / C) - mean * mean;
    float rstd = rsqrtf(var + 1e-5f);

    float* op = out + (size_t)row * C;
#pragma unroll
    for (int i = 0; i < 6; i++) {
        int c = lane + i * 32;
        op[c] = (v[i] - mean) * rstd * s[c] + b[c];
    }
}

// ---------------- SGEMM: C = A[M,K] @ B[K,N] + epilogue --------------------
// tile 128(M) x 64(N) x 16(K), 256 threads, 8x4 per-thread microtile.
// EPI: 0 = +bias (qkv)
//      1 = +bias, scatter to token order with residual add of xin (proj)
//      2 = +bias, exact GELU (mlp1)
//      3 = +bias + res[row,col] (mlp2 -> final output)
#define BM 128
#define BN 64
#define BK 16

template<int EPI>
__global__ __launch_bounds__(256) void sgemm_kernel(const float* __restrict__ A,
                                                    const float* __restrict__ Bm,
                                                    const float* __restrict__ bias,
                                                    const float* __restrict__ res,
                                                    const float* __restrict__ xin,
                                                    float* __restrict__ Cout,
                                                    int M, int N, int K) {
    __shared__ float As[BK][BM + 4];
    __shared__ float Bs[BK][BN];

    int tid = threadIdx.x;
    int tx = tid & 15, ty = tid >> 4;
    int m0 = blockIdx.y * BM;
    int n0 = blockIdx.x * BN;

    float acc[8][4];
#pragma unroll
    for (int r = 0; r < 8; r++)
#pragma unroll
        for (int c = 0; c < 4; c++) acc[r][c] = 0.f;

    int arow  = tid >> 1;
    int ahalf = (tid & 1) * 8;
    int bkk   = tid >> 4;
    int bcol  = (tid & 15) * 4;

    for (int k0 = 0; k0 < K; k0 += BK) {
        const float* ap = A + (size_t)(m0 + arow) * K + k0 + ahalf;
        float4 a0 = *(const float4*)(ap);
        float4 a1 = *(const float4*)(ap + 4);
        As[ahalf + 0][arow] = a0.x;
        As[ahalf + 1][arow] = a0.y;
        As[ahalf + 2][arow] = a0.z;
        As[ahalf + 3][arow] = a0.w;
        As[ahalf + 4][arow] = a1.x;
        As[ahalf + 5][arow] = a1.y;
        As[ahalf + 6][arow] = a1.z;
        As[ahalf + 7][arow] = a1.w;

        float4 b4 = *(const float4*)(Bm + (size_t)(k0 + bkk) * N + n0 + bcol);
        *(float4*)&Bs[bkk][bcol] = b4;
        __syncthreads();

#pragma unroll
        for (int kk = 0; kk < BK; kk++) {
            float a[8], b[4];
#pragma unroll
            for (int r = 0; r < 8; r++) a[r] = As[kk][ty + r * 16];
#pragma unroll
            for (int c = 0; c < 4; c++) b[c] = Bs[kk][tx + c * 16];
#pragma unroll
            for (int r = 0; r < 8; r++)
#pragma unroll
                for (int c = 0; c < 4; c++) acc[r][c] = fmaf(a[r], b[c], acc[r][c]);
        }
        __syncthreads();
    }

#pragma unroll
    for (int r = 0; r < 8; r++) {
        int row = m0 + ty + r * 16;
#pragma unroll
        for (int c = 0; c < 4; c++) {
            int col = n0 + tx + c * 16;
            float v = acc[r][c] + bias[col];
            if (EPI == 0) {
                Cout[(size_t)row * N + col] = v;
            } else if (EPI == 1) {
                int tok = win_row_to_tok(row);
                size_t d = (size_t)tok * C + col;
                Cout[d] = xin[d] + v;
            } else if (EPI == 2) {
                Cout[(size_t)row * N + col] = 0.5f * v * (1.f + erff(v * 0.70710678118654752f));
            } else {
                Cout[(size_t)row * N + col] = v + res[(size_t)row * N + col];
            }
        }
    }
}

// ---------------- windowed attention: one block per (window, head) ---------
__global__ __launch_bounds__(256) void attn_kernel(const float* __restrict__ qkv,
                                                   const float* __restrict__ rpb,
                                                   float* __restrict__ out) {
    int blk = blockIdx.x;          // < NWIN * NH
    int w = blk / NH;
    int h = blk - w * NH;

    __shared__ float qs[64][33];
    __shared__ float ks[64][33];
    __shared__ float vs[64][33];
    __shared__ float ss[64][65];
    __shared__ float sbias[225];

    int tid = threadIdx.x;
    const float* base = qkv + (size_t)w * 64 * (3 * C) + h * HD;

#pragma unroll
    for (int it = 0; it < 2; it++) {
        int idx = tid + it * 256;          // 512 float4 per matrix
        int n = idx >> 3;
        int d4 = (idx & 7) * 4;
        const float* p = base + (size_t)n * (3 * C) + d4;
        float4 q4 = *(const float4*)(p);
        float4 k4 = *(const float4*)(p + C);
        float4 v4 = *(const float4*)(p + 2 * C);
        qs[n][d4] = q4.x; qs[n][d4 + 1] = q4.y; qs[n][d4 + 2] = q4.z; qs[n][d4 + 3] = q4.w;
        ks[n][d4] = k4.x; ks[n][d4 + 1] = k4.y; ks[n][d4 + 2] = k4.z; ks[n][d4 + 3] = k4.w;
        vs[n][d4] = v4.x; vs[n][d4 + 1] = v4.y; vs[n][d4 + 2] = v4.z; vs[n][d4 + 3] = v4.w;
    }
    if (tid < 225) sbias[tid] = rpb[tid * NH + h];
    __syncthreads();

    // S = scale * q k^T + bias  -> ss
    {
        int tx = tid & 15, ty = tid >> 4;
        int nb = ty * 4, mb = tx * 4;
        float acc[4][4];
#pragma unroll
        for (int i = 0; i < 4; i++)
#pragma unroll
            for (int j = 0; j < 4; j++) acc[i][j] = 0.f;
#pragma unroll
        for (int d = 0; d < HD; d++) {
            float a[4], b[4];
#pragma unroll
            for (int i = 0; i < 4; i++) a[i] = qs[nb + i][d];
#pragma unroll
            for (int j = 0; j < 4; j++) b[j] = ks[mb + j][d];
#pragma unroll
            for (int i = 0; i < 4; i++)
#pragma unroll
                for (int j = 0; j < 4; j++) acc[i][j] = fmaf(a[i], b[j], acc[i][j]);
        }
        const float scale = 0.17677669529663687f;   // 1/sqrt(32)
#pragma unroll
        for (int i = 0; i < 4; i++) {
#pragma unroll
            for (int j = 0; j < 4; j++) {
                int n = nb + i, m = mb + j;
                int iy = n >> 3, ix = n & 7, jy = m >> 3, jx = m & 7;
                int ridx = (iy - jy + 7) * 15 + (ix - jx + 7);
                ss[n][m] = acc[i][j] * scale + sbias[ridx];
            }
        }
    }
    __syncthreads();

    // row softmax: warp wid handles rows wid*8 .. wid*8+7
    {
        int wid = tid >> 5, lane = tid & 31;
#pragma unroll
        for (int rr = 0; rr < 8; rr++) {
            int n = wid * 8 + rr;
            float e0 = ss[n][lane];
            float e1 = ss[n][lane + 32];
            float mx = fmaxf(e0, e1);
#pragma unroll
            for (int o = 16; o > 0; o >>= 1) mx = fmaxf(mx, __shfl_xor_sync(0xffffffffu, mx, o));
            e0 = expf(e0 - mx);
            e1 = expf(e1 - mx);
            float sum = e0 + e1;
#pragma unroll
            for (int o = 16; o > 0; o >>= 1) sum += __shfl_xor_sync(0xffffffffu, sum, o);
            float inv = 1.f / sum;
            ss[n][lane] = e0 * inv;
            ss[n][lane + 32] = e1 * inv;
        }
    }
    __syncthreads();

    // O = S @ V : thread handles (n, d0..d0+7)
    {
        int n = tid >> 2;
        int d0 = (tid & 3) * 8;
        float o[8];
#pragma unroll
        for (int u = 0; u < 8; u++) o[u] = 0.f;
#pragma unroll
        for (int m = 0; m < 64; m++) {
            float sv = ss[n][m];
#pragma unroll
            for (int u = 0; u < 8; u++) o[u] = fmaf(sv, vs[m][d0 + u], o[u]);
        }
        float* op = out + (size_t)(w * 64 + n) * C + h * HD + d0;
#pragma unroll
        for (int u = 0; u < 8; u++) op[u] = o[u];
    }
}

// ---------------- launch ---------------------------------------------------
extern "C" void kernel_launch(void* const* d_in, const int* in_sizes, int n_in,
                              void* d_out, int out_size) {
    const float* x      = (const float*)d_in[0];
    const float* qkv_w  = (const float*)d_in[1];
    const float* qkv_b  = (const float*)d_in[2];
    const float* proj_w = (const float*)d_in[3];
    const float* proj_b = (const float*)d_in[4];
    const float* rpb    = (const float*)d_in[5];
    const float* n1s    = (const float*)d_in[6];
    const float* n1b    = (const float*)d_in[7];
    const float* n2s    = (const float*)d_in[8];
    const float* n2b    = (const float*)d_in[9];
    const float* w1     = (const float*)d_in[10];
    const float* b1     = (const float*)d_in[11];
    const float* w2     = (const float*)d_in[12];
    const float* b2     = (const float*)d_in[13];
    float* out = (float*)d_out;

    float *xw, *qkv, *attn, *x1, *xn2, *h1;
    cudaGetSymbolAddress((void**)&xw,   g_xw);
    cudaGetSymbolAddress((void**)&qkv,  g_qkv);
    cudaGetSymbolAddress((void**)&attn, g_attn);
    cudaGetSymbolAddress((void**)&x1,   g_x1);
    cudaGetSymbolAddress((void**)&xn2,  g_xn2);
    cudaGetSymbolAddress((void**)&h1,   g_h1);

    const int M = NTOK;

    // 1. LN1 + shift-roll + window partition
    ln_kernel<true><<<NTOK / 8, 256>>>(x, n1s, n1b, xw);

    // 2. QKV GEMM: [M,192] @ [192,576] + bias
    sgemm_kernel<0><<<dim3((3 * C) / BN, M / BM), 256>>>(xw, qkv_w, qkv_b,
                                                         nullptr, nullptr, qkv,
                                                         M, 3 * C, C);

    // 3. windowed attention
    attn_kernel<<<NWIN * NH, 256>>>(qkv, rpb, attn);

    // 4. proj GEMM + window-reverse + roll-back + residual -> x1 (token order)
    sgemm_kernel<1><<<dim3(C / BN, M / BM), 256>>>(attn, proj_w, proj_b,
                                                   nullptr, x, x1,
                                                   M, C, C);

    // 5. LN2
    ln_kernel<false><<<NTOK / 8, 256>>>(x1, n2s, n2b, xn2);

    // 6. MLP up + GELU
    sgemm_kernel<2><<<dim3((4 * C) / BN, M / BM), 256>>>(xn2, w1, b1,
                                                         nullptr, nullptr, h1,
                                                         M, 4 * C, C);

    // 7. MLP down + residual -> output
    sgemm_kernel<3><<<dim3(C / BN, M / BM), 256>>>(h1, w2, b2,
                                                   x1, nullptr, out,
                                                   M, C, 4 * C);
}

// round 2
// speedup vs baseline: 2.7424x; 2.7424x over previous
#include <cuda_runtime.h>
#include <math.h>
#include <stdint.h>

// Problem constants (fixed by the dataset)
#define BATCH   8
#define HW      128
#define LTOK    16384
#define C       192
#define WS      8
#define SHIFT   4
#define NH      6
#define HD      32
#define NWIN    2048
#define NTOK    131072

// ---------------- scratch (device globals; no cudaMalloc allowed) ----------
__device__ float g_xw  [(size_t)NTOK * C];
__device__ float g_qkv [(size_t)NTOK * 3 * C];
__device__ float g_attn[(size_t)NTOK * C];
__device__ float g_x1  [(size_t)NTOK * C];
__device__ float g_xn2 [(size_t)NTOK * C];
__device__ float g_h1  [(size_t)NTOK * 4 * C];
// tf32-rounded weight copies
__device__ float g_wqkv [C * 3 * C];
__device__ float g_wproj[C * C];
__device__ float g_w1   [C * 4 * C];
__device__ float g_w2   [4 * C * C];

__device__ __forceinline__ uint32_t f2tf(float x) {
    uint32_t r;
    asm("cvt.rna.tf32.f32 %0, %1;" : "=r"(r) : "f"(x));
    return r;
}
__device__ __forceinline__ float f2tf_f(float x) { return __uint_as_float(f2tf(x)); }

__device__ __forceinline__ void cpasync16(uint32_t dst, const void* src) {
    asm volatile("cp.async.cg.shared.global [%0], [%1], 16;" :: "r"(dst), "l"(src));
}

__device__ __forceinline__ void mma_tf32(float* d, const uint32_t* a, const uint32_t* b) {
    asm volatile(
        "mma.sync.aligned.m16n8k8.row.col.f32.tf32.tf32.f32 "
        "{%0,%1,%2,%3}, {%4,%5,%6,%7}, {%8,%9}, {%0,%1,%2,%3};"
        : "+f"(d[0]), "+f"(d[1]), "+f"(d[2]), "+f"(d[3])
        : "r"(a[0]), "r"(a[1]), "r"(a[2]), "r"(a[3]), "r"(b[0]), "r"(b[1]));
}

// window-row (w*64+n) -> flat token index, accounting for the -shift roll
__device__ __forceinline__ int win_row_to_tok(int row) {
    int w  = row >> 6;
    int n  = row & 63;
    int b  = w >> 8;
    int wy = (w >> 4) & 15;
    int wx = w & 15;
    int iy = n >> 3;
    int ix = n & 7;
    int hr = (wy * WS + iy + SHIFT) & (HW - 1);
    int wr = (wx * WS + ix + SHIFT) & (HW - 1);
    return (b << 14) + (hr << 7) + wr;
}

// ---------------- weight tf32 rounding -------------------------------------
__global__ void roundcopy_kernel(const float* __restrict__ in, float* __restrict__ out, int n) {
    int i = blockIdx.x * 256 + threadIdx.x;
    if (i < n) out[i] = f2tf_f(in[i]);
}

// ---------------- LayerNorm (one warp per token); output tf32-rounded ------
template<bool GATHER>
__global__ __launch_bounds__(256) void ln_kernel(const float* __restrict__ x,
                                                 const float* __restrict__ s,
                                                 const float* __restrict__ b,
                                                 float* __restrict__ out) {
    int warp = threadIdx.x >> 5;
    int lane = threadIdx.x & 31;
    int row  = blockIdx.x * 8 + warp;
    int src  = GATHER ? win_row_to_tok(row) : row;
    const float* xp = x + (size_t)src * C;

    float v[6];
    float sum = 0.f, sq = 0.f;
#pragma unroll
    for (int i = 0; i < 6; i++) {
        v[i] = xp[lane + i * 32];
        sum += v[i];
        sq  += v[i] * v[i];
    }
#pragma unroll
    for (int o = 16; o > 0; o >>= 1) {
        sum += __shfl_xor_sync(0xffffffffu, sum, o);
        sq  += __shfl_xor_sync(0xffffffffu, sq, o);
    }
    float mean = sum * (1.f / C);
    float var  = sq * (1.f / C) - mean * mean;
    float rstd = rsqrtf(var + 1e-5f);

    float* op = out + (size_t)row * C;
#pragma unroll
    for (int i = 0; i < 6; i++) {
        int c = lane + i * 32;
        op[c] = f2tf_f((v[i] - mean) * rstd * s[c] + b[c]);
    }
}

// ---------------- tf32 MMA GEMM: C = A[M,K] @ B[K,N] + epilogue ------------
// tile 256(M) x 64(N) x 16(K), 256 threads = 8 warps (4 M x 2 N),
// warp tile 64x32 = 4x4 m16n8k8 atoms. cp.async double buffer, XOR swizzle.
// EPI: 0 = +bias (qkv, feeds fp32 attention)
//      1 = +bias, scatter to token order with residual add of xin (proj)
//      2 = +bias, exact GELU, tf32-rounded (mlp1)
//      3 = +bias + res[row,col] (mlp2 -> final output)
#define GBM 256
#define GBN 64
#define GBK 16

template<int EPI>
__global__ __launch_bounds__(256, 2) void mma_gemm(const float* __restrict__ A,
                                                   const float* __restrict__ Bm,
                                                   const float* __restrict__ bias,
                                                   const float* __restrict__ res,
                                                   const float* __restrict__ xin,
                                                   float* __restrict__ Cout,
                                                   int M, int N, int K) {
    __shared__ uint32_t As[2][GBM * GBK];   // [row][k^((row&6)<<1)]
    __shared__ uint32_t Bs[2][GBK * GBN];   // [k][n^((k&3)<<3)]

    int tid  = threadIdx.x;
    int wid  = tid >> 5, lane = tid & 31;
    int g    = lane >> 2, tig = lane & 3;
    int wm   = (wid & 3) * 64;
    int wn   = (wid >> 2) * 32;
    int m0   = blockIdx.y * GBM;
    int n0   = blockIdx.x * GBN;

    int ar = tid >> 2;            // A load row (0..63, +64*p)
    int ak = (tid & 3) * 4;       // A load k0
    int bk = tid >> 4;            // B load k (0..15)
    int bn = (tid & 15) * 4;      // B load n0

    uint32_t sa = (uint32_t)__cvta_generic_to_shared(&As[0][0]);
    uint32_t sb = (uint32_t)__cvta_generic_to_shared(&Bs[0][0]);

    float acc[4][4][4];
#pragma unroll
    for (int i = 0; i < 4; i++)
#pragma unroll
        for (int j = 0; j < 4; j++)
#pragma unroll
            for (int q = 0; q < 4; q++) acc[i][j][q] = 0.f;

    const int nk = K / GBK;

    // issue tile kt into buffer buf
    auto issue = [&](int kt, int buf) {
        const float* ga = A + (size_t)m0 * K + kt * GBK;
#pragma unroll
        for (int p = 0; p < 4; p++) {
            int row = ar + p * 64;
            uint32_t d = sa + (uint32_t)(buf * (GBM * GBK) + row * GBK + (ak ^ ((row & 6) << 1))) * 4u;
            cpasync16(d, ga + (size_t)row * K + ak);
        }
        const float* gb = Bm + (size_t)(kt * GBK + bk) * N + n0 + bn;
        uint32_t d = sb + (uint32_t)(buf * (GBK * GBN) + (bk << 6) + (bn ^ ((bk & 3) << 3))) * 4u;
        cpasync16(d, gb);
        asm volatile("cp.async.commit_group;" ::: "memory");
    };

    issue(0, 0);
    int buf = 0;
    for (int kt = 0; kt < nk; kt++) {
        if (kt + 1 < nk) {
            issue(kt + 1, buf ^ 1);
            asm volatile("cp.async.wait_group 1;" ::: "memory");
        } else {
            asm volatile("cp.async.wait_group 0;" ::: "memory");
        }
        __syncthreads();

        const uint32_t* as = As[buf];
        const uint32_t* bs = Bs[buf];
#pragma unroll
        for (int kk = 0; kk < GBK; kk += 8) {
            uint32_t af[4][4], bf[4][2];
            int k0 = kk + tig, k1 = kk + tig + 4;
            int xb = (tig << 3);   // (k&3)<<3, same for k0 and k1
#pragma unroll
            for (int nb = 0; nb < 4; nb++) {
                int n = wn + nb * 8 + g;
                bf[nb][0] = bs[(k0 << 6) + (n ^ xb)];
                bf[nb][1] = bs[(k1 << 6) + (n ^ xb)];
            }
#pragma unroll
            for (int ma = 0; ma < 4; ma++) {
                int r  = wm + ma * 16 + g;
                int r8 = r + 8;
                int xr  = (r & 6) << 1;
                int xr8 = (r8 & 6) << 1;
                af[ma][0] = as[(r  << 4) + (k0 ^ xr)];
                af[ma][1] = as[(r8 << 4) + (k0 ^ xr8)];
                af[ma][2] = as[(r  << 4) + (k1 ^ xr)];
                af[ma][3] = as[(r8 << 4) + (k1 ^ xr8)];
            }
#pragma unroll
            for (int ma = 0; ma < 4; ma++)
#pragma unroll
                for (int nb = 0; nb < 4; nb++)
                    mma_tf32(acc[ma][nb], af[ma], bf[nb]);
        }
        __syncthreads();
        buf ^= 1;
    }

    // epilogue
#pragma unroll
    for (int ma = 0; ma < 4; ma++) {
        int rlo = m0 + wm + ma * 16 + g;
        int rhi = rlo + 8;
#pragma unroll
        for (int nb = 0; nb < 4; nb++) {
            int col = n0 + wn + nb * 8 + tig * 2;
            float bi0 = bias[col], bi1 = bias[col + 1];
            float v00 = acc[ma][nb][0] + bi0, v01 = acc[ma][nb][1] + bi1;
            float v10 = acc[ma][nb][2] + bi0, v11 = acc[ma][nb][3] + bi1;
            if (EPI == 0) {
                *(float2*)&Cout[(size_t)rlo * N + col] = make_float2(v00, v01);
                *(float2*)&Cout[(size_t)rhi * N + col] = make_float2(v10, v11);
            } else if (EPI == 1) {
                int t0 = win_row_to_tok(rlo);
                int t1 = win_row_to_tok(rhi);
                size_t d0 = (size_t)t0 * C + col;
                size_t d1 = (size_t)t1 * C + col;
                Cout[d0]     = xin[d0]     + v00;
                Cout[d0 + 1] = xin[d0 + 1] + v01;
                Cout[d1]     = xin[d1]     + v10;
                Cout[d1 + 1] = xin[d1 + 1] + v11;
            } else if (EPI == 2) {
                const float is2 = 0.70710678118654752f;
                v00 = 0.5f * v00 * (1.f + erff(v00 * is2));
                v01 = 0.5f * v01 * (1.f + erff(v01 * is2));
                v10 = 0.5f * v10 * (1.f + erff(v10 * is2));
                v11 = 0.5f * v11 * (1.f + erff(v11 * is2));
                *(float2*)&Cout[(size_t)rlo * N + col] = make_float2(f2tf_f(v00), f2tf_f(v01));
                *(float2*)&Cout[(size_t)rhi * N + col] = make_float2(f2tf_f(v10), f2tf_f(v11));
            } else {
                size_t d0 = (size_t)rlo * N + col;
                size_t d1 = (size_t)rhi * N + col;
                *(float2*)&Cout[d0] = make_float2(v00 + res[d0], v01 + res[d0 + 1]);
                *(float2*)&Cout[d1] = make_float2(v10 + res[d1], v11 + res[d1 + 1]);
            }
        }
    }
}

// ---------------- windowed attention: one block per (window, head) ---------
__global__ __launch_bounds__(256) void attn_kernel(const float* __restrict__ qkv,
                                                   const float* __restrict__ rpb,
                                                   float* __restrict__ out) {
    int blk = blockIdx.x;
    int w = blk / NH;
    int h = blk - w * NH;

    __shared__ float qs[64][33];
    __shared__ float ks[64][33];
    __shared__ float vs[64][33];
    __shared__ float ss[64][65];
    __shared__ float sbias[225];

    int tid = threadIdx.x;
    const float* base = qkv + (size_t)w * 64 * (3 * C) + h * HD;

#pragma unroll
    for (int it = 0; it < 2; it++) {
        int idx = tid + it * 256;
        int n = idx >> 3;
        int d4 = (idx & 7) * 4;
        const float* p = base + (size_t)n * (3 * C) + d4;
        float4 q4 = *(const float4*)(p);
        float4 k4 = *(const float4*)(p + C);
        float4 v4 = *(const float4*)(p + 2 * C);
        qs[n][d4] = q4.x; qs[n][d4 + 1] = q4.y; qs[n][d4 + 2] = q4.z; qs[n][d4 + 3] = q4.w;
        ks[n][d4] = k4.x; ks[n][d4 + 1] = k4.y; ks[n][d4 + 2] = k4.z; ks[n][d4 + 3] = k4.w;
        vs[n][d4] = v4.x; vs[n][d4 + 1] = v4.y; vs[n][d4 + 2] = v4.z; vs[n][d4 + 3] = v4.w;
    }
    if (tid < 225) sbias[tid] = rpb[tid * NH + h];
    __syncthreads();

    {
        int tx = tid & 15, ty = tid >> 4;
        int nb = ty * 4, mb = tx * 4;
        float acc[4][4];
#pragma unroll
        for (int i = 0; i < 4; i++)
#pragma unroll
            for (int j = 0; j < 4; j++) acc[i][j] = 0.f;
#pragma unroll
        for (int d = 0; d < HD; d++) {
            float a[4], b[4];
#pragma unroll
            for (int i = 0; i < 4; i++) a[i] = qs[nb + i][d];
#pragma unroll
            for (int j = 0; j < 4; j++) b[j] = ks[mb + j][d];
#pragma unroll
            for (int i = 0; i < 4; i++)
#pragma unroll
                for (int j = 0; j < 4; j++) acc[i][j] = fmaf(a[i], b[j], acc[i][j]);
        }
        const float scale = 0.17677669529663687f;
#pragma unroll
        for (int i = 0; i < 4; i++) {
#pragma unroll
            for (int j = 0; j < 4; j++) {
                int n = nb + i, m = mb + j;
                int iy = n >> 3, ix = n & 7, jy = m >> 3, jx = m & 7;
                int ridx = (iy - jy + 7) * 15 + (ix - jx + 7);
                ss[n][m] = acc[i][j] * scale + sbias[ridx];
            }
        }
    }
    __syncthreads();

    {
        int wid = tid >> 5, lane = tid & 31;
#pragma unroll
        for (int rr = 0; rr < 8; rr++) {
            int n = wid * 8 + rr;
            float e0 = ss[n][lane];
            float e1 = ss[n][lane + 32];
            float mx = fmaxf(e0, e1);
#pragma unroll
            for (int o = 16; o > 0; o >>= 1) mx = fmaxf(mx, __shfl_xor_sync(0xffffffffu, mx, o));
            e0 = expf(e0 - mx);
            e1 = expf(e1 - mx);
            float sum = e0 + e1;
#pragma unroll
            for (int o = 16; o > 0; o >>= 1) sum += __shfl_xor_sync(0xffffffffu, sum, o);
            float inv = 1.f / sum;
            ss[n][lane] = e0 * inv;
            ss[n][lane + 32] = e1 * inv;
        }
    }
    __syncthreads();

    {
        int n = tid >> 2;
        int d0 = (tid & 3) * 8;
        float o[8];
#pragma unroll
        for (int u = 0; u < 8; u++) o[u] = 0.f;
#pragma unroll
        for (int m = 0; m < 64; m++) {
            float sv = ss[n][m];
#pragma unroll
            for (int u = 0; u < 8; u++) o[u] = fmaf(sv, vs[m][d0 + u], o[u]);
        }
        float* op = out + (size_t)(w * 64 + n) * C + h * HD + d0;
#pragma unroll
        for (int u = 0; u < 8; u++) op[u] = f2tf_f(o[u]);   // tf32-round for proj GEMM
    }
}

// ---------------- launch ---------------------------------------------------
extern "C" void kernel_launch(void* const* d_in, const int* in_sizes, int n_in,
                              void* d_out, int out_size) {
    const float* x      = (const float*)d_in[0];
    const float* qkv_w  = (const float*)d_in[1];
    const float* qkv_b  = (const float*)d_in[2];
    const float* proj_w = (const float*)d_in[3];
    const float* proj_b = (const float*)d_in[4];
    const float* rpb    = (const float*)d_in[5];
    const float* n1s    = (const float*)d_in[6];
    const float* n1b    = (const float*)d_in[7];
    const float* n2s    = (const float*)d_in[8];
    const float* n2b    = (const float*)d_in[9];
    const float* w1     = (const float*)d_in[10];
    const float* b1     = (const float*)d_in[11];
    const float* w2     = (const float*)d_in[12];
    const float* b2     = (const float*)d_in[13];
    float* out = (float*)d_out;

    float *xw, *qkv, *attn, *x1, *xn2, *h1, *wqkv, *wproj, *ww1, *ww2;
    cudaGetSymbolAddress((void**)&xw,    g_xw);
    cudaGetSymbolAddress((void**)&qkv,   g_qkv);
    cudaGetSymbolAddress((void**)&attn,  g_attn);
    cudaGetSymbolAddress((void**)&x1,    g_x1);
    cudaGetSymbolAddress((void**)&xn2,   g_xn2);
    cudaGetSymbolAddress((void**)&h1,    g_h1);
    cudaGetSymbolAddress((void**)&wqkv,  g_wqkv);
    cudaGetSymbolAddress((void**)&wproj, g_wproj);
    cudaGetSymbolAddress((void**)&ww1,   g_w1);
    cudaGetSymbolAddress((void**)&ww2,   g_w2);

    const int M = NTOK;

    // tf32-round weights
    roundcopy_kernel<<<(C * 3 * C + 255) / 256, 256>>>(qkv_w,  wqkv,  C * 3 * C);
    roundcopy_kernel<<<(C * C + 255) / 256,     256>>>(proj_w, wproj, C * C);
    roundcopy_kernel<<<(C * 4 * C + 255) / 256, 256>>>(w1,     ww1,   C * 4 * C);
    roundcopy_kernel<<<(4 * C * C + 255) / 256, 256>>>(w2,     ww2,   4 * C * C);

    // 1. LN1 + shift-roll + window partition (tf32-rounded)
    ln_kernel<true><<<NTOK / 8, 256>>>(x, n1s, n1b, xw);

    // 2. QKV GEMM
    mma_gemm<0><<<dim3((3 * C) / GBN, M / GBM), 256>>>(xw, wqkv, qkv_b,
                                                       nullptr, nullptr, qkv,
                                                       M, 3 * C, C);

    // 3. windowed attention
    attn_kernel<<<NWIN * NH, 256>>>(qkv, rpb, attn);

    // 4. proj GEMM + window-reverse + roll-back + residual -> x1 (token order)
    mma_gemm<1><<<dim3(C / GBN, M / GBM), 256>>>(attn, wproj, proj_b,
                                                 nullptr, x, x1,
                                                 M, C, C);

    // 5. LN2 (tf32-rounded)
    ln_kernel<false><<<NTOK / 8, 256>>>(x1, n2s, n2b, xn2);

    // 6. MLP up + GELU (tf32-rounded)
    mma_gemm<2><<<dim3((4 * C) / GBN, M / GBM), 256>>>(xn2, ww1, b1,
                                                       nullptr, nullptr, h1,
                                                       M, 4 * C, C);

    // 7. MLP down + residual -> output
    mma_gemm<3><<<dim3(C / GBN, M / GBM), 256>>>(h1, ww2, b2,
                                                 x1, nullptr, out,
                                                 M, C, 4 * C);
}

// round 3
// speedup vs baseline: 5.4044x; 1.9707x over previous
#include <cuda_runtime.h>
#include <cuda_bf16.h>
#include <math.h>
#include <stdint.h>

// Problem constants
#define BATCH   8
#define HW      128
#define LTOK    16384
#define C       192
#define WS      8
#define SHIFT   4
#define NH      6
#define HD      32
#define NWIN    2048
#define NTOK    131072

// ---------------- scratch (device globals) ---------------------------------
__device__ __nv_bfloat16 g_xw  [(size_t)NTOK * C];
__device__ __nv_bfloat16 g_qkv [(size_t)NTOK * 3 * C];
__device__ __nv_bfloat16 g_attn[(size_t)NTOK * C];
__device__ float         g_x1  [(size_t)NTOK * C];
__device__ __nv_bfloat16 g_xn2 [(size_t)NTOK * C];
__device__ __nv_bfloat16 g_h1  [(size_t)NTOK * 4 * C];
__device__ __nv_bfloat16 g_wqkv [C * 3 * C];
__device__ __nv_bfloat16 g_wproj[C * C];
__device__ __nv_bfloat16 g_w1   [C * 4 * C];
__device__ __nv_bfloat16 g_w2   [4 * C * C];
__device__ float         g_abias[NH * 64 * 64];

// ---------------- helpers --------------------------------------------------
__device__ __forceinline__ void cpasync16(uint32_t dst, const void* src) {
    asm volatile("cp.async.cg.shared.global [%0], [%1], 16;" :: "r"(dst), "l"(src));
}
__device__ __forceinline__ void ldsm_x4(uint32_t* r, uint32_t addr) {
    asm volatile("ldmatrix.sync.aligned.m8n8.x4.shared.b16 {%0,%1,%2,%3}, [%4];"
        : "=r"(r[0]), "=r"(r[1]), "=r"(r[2]), "=r"(r[3]) : "r"(addr));
}
__device__ __forceinline__ void ldsm_x4_t(uint32_t* r, uint32_t addr) {
    asm volatile("ldmatrix.sync.aligned.m8n8.x4.trans.shared.b16 {%0,%1,%2,%3}, [%4];"
        : "=r"(r[0]), "=r"(r[1]), "=r"(r[2]), "=r"(r[3]) : "r"(addr));
}
__device__ __forceinline__ void mma_bf16(float* d, const uint32_t* a, const uint32_t* b) {
    asm volatile(
        "mma.sync.aligned.m16n8k16.row.col.f32.bf16.bf16.f32 "
        "{%0,%1,%2,%3}, {%4,%5,%6,%7}, {%8,%9}, {%0,%1,%2,%3};"
        : "+f"(d[0]), "+f"(d[1]), "+f"(d[2]), "+f"(d[3])
        : "r"(a[0]), "r"(a[1]), "r"(a[2]), "r"(a[3]), "r"(b[0]), "r"(b[1]));
}
__device__ __forceinline__ uint32_t packbf(float lo, float hi) {
    uint32_t r;
    asm("cvt.rn.bf16x2.f32 %0, %1, %2;" : "=r"(r) : "f"(hi), "f"(lo));
    return r;
}
// exp via FMA-pipe polynomial (avoids MUFU EX2)
__device__ __forceinline__ float fast_exp(float x) {
    float t = fmaxf(x * 1.4426950408889634f, -100.f);
    float z = t + 12582912.f;               // round-to-nearest-int magic (1.5*2^23)
    int   ni = __float_as_int(z);
    float nf = z - 12582912.f;
    float f  = t - nf;
    float p = 1.33335581e-3f;
    p = fmaf(p, f, 9.61812910e-3f);
    p = fmaf(p, f, 5.55041087e-2f);
    p = fmaf(p, f, 2.40226507e-1f);
    p = fmaf(p, f, 6.93147181e-1f);
    p = fmaf(p, f, 1.0f);
    float sc = __int_as_float((((ni & 0x7FFFFF) - 0x400000) + 127) << 23);
    return p * sc;
}

// window-row (w*64+n) -> flat token index, accounting for the -shift roll
__device__ __forceinline__ int win_row_to_tok(int row) {
    int w  = row >> 6;
    int n  = row & 63;
    int b  = w >> 8;
    int wy = (w >> 4) & 15;
    int wx = w & 15;
    int iy = n >> 3;
    int ix = n & 7;
    int hr = (wy * WS + iy + SHIFT) & (HW - 1);
    int wr = (wx * WS + ix + SHIFT) & (HW - 1);
    return (b << 14) + (hr << 7) + wr;
}

// ---------------- small prep kernels ---------------------------------------
__global__ void w2bf_kernel(const float* __restrict__ in, __nv_bfloat16* __restrict__ out, int n) {
    int i = blockIdx.x * 256 + threadIdx.x;
    if (i < n) out[i] = __float2bfloat16(in[i]);
}
__global__ void abias_kernel(const float* __restrict__ rpb, float* __restrict__ tab) {
    int i = blockIdx.x * 256 + threadIdx.x;   // < NH*64*64
    if (i >= NH * 64 * 64) return;
    int h = i >> 12;
    int n = (i >> 6) & 63;
    int m = i & 63;
    int iy = n >> 3, ix = n & 7, jy = m >> 3, jx = m & 7;
    int ridx = (iy - jy + 7) * 15 + (ix - jx + 7);
    tab[i] = rpb[ridx * NH + h];
}

// ---------------- LayerNorm (one warp per token) -> bf16 -------------------
template<bool GATHER>
__global__ __launch_bounds__(256) void ln_kernel(const float* __restrict__ x,
                                                 const float* __restrict__ s,
                                                 const float* __restrict__ b,
                                                 __nv_bfloat16* __restrict__ out) {
    int warp = threadIdx.x >> 5;
    int lane = threadIdx.x & 31;
    int row  = blockIdx.x * 8 + warp;
    int src  = GATHER ? win_row_to_tok(row) : row;
    const float* xp = x + (size_t)src * C;

    float v[6];
    float sum = 0.f, sq = 0.f;
#pragma unroll
    for (int i = 0; i < 6; i++) {
        v[i] = xp[lane + i * 32];
        sum += v[i];
        sq  += v[i] * v[i];
    }
#pragma unroll
    for (int o = 16; o > 0; o >>= 1) {
        sum += __shfl_xor_sync(0xffffffffu, sum, o);
        sq  += __shfl_xor_sync(0xffffffffu, sq, o);
    }
    float mean = sum * (1.f / C);
    float var  = sq * (1.f / C) - mean * mean;
    float rstd = rsqrtf(var + 1e-5f);

    __nv_bfloat16* op = out + (size_t)row * C;
#pragma unroll
    for (int i = 0; i < 6; i++) {
        int c = lane + i * 32;
        op[c] = __float2bfloat16((v[i] - mean) * rstd * s[c] + b[c]);
    }
}

// ---------------- bf16 MMA GEMM: C = A[M,K] @ B[K,N] + epilogue ------------
// tile 256x64x32, 256 threads = 8 warps (4M x 2N), warp tile 64x32.
// EPI: 0 = +bias -> bf16 (qkv)
//      1 = +bias, scatter token order + residual xin -> fp32 (proj)
//      2 = +bias, exact GELU -> bf16 (mlp1)
//      3 = +bias + res -> fp32 (mlp2, final)
#define GBM 256
#define GBN 64
#define GBK 32

template<int EPI>
__global__ __launch_bounds__(256, 2) void bgemm(const __nv_bfloat16* __restrict__ A,
                                                const __nv_bfloat16* __restrict__ Bm,
                                                const float* __restrict__ bias,
                                                const float* __restrict__ res,
                                                const float* __restrict__ xin,
                                                void* __restrict__ outv,
                                                int M, int N, int K) {
    __shared__ __align__(16) __nv_bfloat16 As[2][GBM * GBK];
    __shared__ __align__(16) __nv_bfloat16 Bs[2][GBK * GBN];

    int tid  = threadIdx.x;
    int wid  = tid >> 5, lane = tid & 31;
    int wm   = (wid & 3) * 64;
    int wn   = (wid >> 2) * 32;
    int m0   = blockIdx.y * GBM;
    int n0   = blockIdx.x * GBN;

    uint32_t sa = (uint32_t)__cvta_generic_to_shared(&As[0][0]);
    uint32_t sb = (uint32_t)__cvta_generic_to_shared(&Bs[0][0]);

    // per-thread ldmatrix byte offsets (within one buffer)
    uint32_t aoff[4][2], boff[2][2];
#pragma unroll
    for (int ma = 0; ma < 4; ma++)
#pragma unroll
        for (int ks = 0; ks < 2; ks++) {
            int row = wm + ma * 16 + (lane & 7) + 8 * ((lane >> 3) & 1);
            int ch  = 2 * ks + (lane >> 4);
            aoff[ma][ks] = row * 64 + ((ch ^ ((row >> 1) & 3)) << 4);
        }
#pragma unroll
    for (int np = 0; np < 2; np++)
#pragma unroll
        for (int ks = 0; ks < 2; ks++) {
            int k  = ks * 16 + (lane & 7) + 8 * ((lane >> 3) & 1);
            int cn = (wn >> 3) + np * 2 + (lane >> 4);
            boff[np][ks] = k * 128 + ((cn ^ (k & 7)) << 4);
        }

    float acc[4][4][4];
#pragma unroll
    for (int i = 0; i < 4; i++)
#pragma unroll
        for (int j = 0; j < 4; j++)
#pragma unroll
            for (int q = 0; q < 4; q++) acc[i][j][q] = 0.f;

    const int nk = K / GBK;
    int arow = tid >> 2, ac = tid & 3;
    int bk = tid >> 3,  bcn = tid & 7;
    uint32_t adst0 = arow * 64 + ((ac ^ ((arow >> 1) & 3)) << 4);
    uint32_t bdst  = bk * 128 + ((bcn ^ (bk & 7)) << 4);

    auto issue = [&](int kt, int buf) {
        const __nv_bfloat16* ga = A + (size_t)m0 * K + kt * GBK + ac * 8;
#pragma unroll
        for (int p = 0; p < 4; p++) {
            int row = arow + p * 64;
            cpasync16(sa + buf * (GBM * GBK * 2) + adst0 + p * (64 * 64),
                      ga + (size_t)row * K);
        }
        cpasync16(sb + buf * (GBK * GBN * 2) + bdst,
                  Bm + (size_t)(kt * GBK + bk) * N + n0 + bcn * 8);
        asm volatile("cp.async.commit_group;" ::: "memory");
    };

    issue(0, 0);
    int buf = 0;
    for (int kt = 0; kt < nk; kt++) {
        if (kt + 1 < nk) {
            issue(kt + 1, buf ^ 1);
            asm volatile("cp.async.wait_group 1;" ::: "memory");
        } else {
            asm volatile("cp.async.wait_group 0;" ::: "memory");
        }
        __syncthreads();

        uint32_t ab = sa + buf * (GBM * GBK * 2);
        uint32_t bb = sb + buf * (GBK * GBN * 2);
#pragma unroll
        for (int ks = 0; ks < 2; ks++) {
            uint32_t af[4][4], bf[4][2];
#pragma unroll
            for (int ma = 0; ma < 4; ma++) ldsm_x4(af[ma], ab + aoff[ma][ks]);
#pragma unroll
            for (int np = 0; np < 2; np++) {
                uint32_t t4[4];
                ldsm_x4_t(t4, bb + boff[np][ks]);
                bf[np * 2][0] = t4[0]; bf[np * 2][1] = t4[1];
                bf[np * 2 + 1][0] = t4[2]; bf[np * 2 + 1][1] = t4[3];
            }
#pragma unroll
            for (int ma = 0; ma < 4; ma++)
#pragma unroll
                for (int nb = 0; nb < 4; nb++)
                    mma_bf16(acc[ma][nb], af[ma], bf[nb]);
        }
        __syncthreads();
        buf ^= 1;
    }

    int g = lane >> 2, tig = lane & 3;
#pragma unroll
    for (int ma = 0; ma < 4; ma++) {
        int rlo = m0 + wm + ma * 16 + g;
        int rhi = rlo + 8;
#pragma unroll
        for (int nb = 0; nb < 4; nb++) {
            int col = n0 + wn + nb * 8 + tig * 2;
            float bi0 = bias[col], bi1 = bias[col + 1];
            float v00 = acc[ma][nb][0] + bi0, v01 = acc[ma][nb][1] + bi1;
            float v10 = acc[ma][nb][2] + bi0, v11 = acc[ma][nb][3] + bi1;
            if (EPI == 0) {
                __nv_bfloat16* out = (__nv_bfloat16*)outv;
                *(uint32_t*)&out[(size_t)rlo * N + col] = packbf(v00, v01);
                *(uint32_t*)&out[(size_t)rhi * N + col] = packbf(v10, v11);
            } else if (EPI == 1) {
                float* out = (float*)outv;
                int t0 = win_row_to_tok(rlo);
                int t1 = win_row_to_tok(rhi);
                size_t d0 = (size_t)t0 * C + col;
                size_t d1 = (size_t)t1 * C + col;
                out[d0]     = xin[d0]     + v00;
                out[d0 + 1] = xin[d0 + 1] + v01;
                out[d1]     = xin[d1]     + v10;
                out[d1 + 1] = xin[d1 + 1] + v11;
            } else if (EPI == 2) {
                const float is2 = 0.70710678118654752f;
                v00 = 0.5f * v00 * (1.f + erff(v00 * is2));
                v01 = 0.5f * v01 * (1.f + erff(v01 * is2));
                v10 = 0.5f * v10 * (1.f + erff(v10 * is2));
                v11 = 0.5f * v11 * (1.f + erff(v11 * is2));
                __nv_bfloat16* out = (__nv_bfloat16*)outv;
                *(uint32_t*)&out[(size_t)rlo * N + col] = packbf(v00, v01);
                *(uint32_t*)&out[(size_t)rhi * N + col] = packbf(v10, v11);
            } else {
                float* out = (float*)outv;
                size_t d0 = (size_t)rlo * N + col;
                size_t d1 = (size_t)rhi * N + col;
                *(float2*)&out[d0] = make_float2(v00 + res[d0], v01 + res[d0 + 1]);
                *(float2*)&out[d1] = make_float2(v10 + res[d1], v11 + res[d1 + 1]);
            }
        }
    }
}

// ---------------- attention: bf16 mma, block = (window, head), 128 thr -----
__global__ __launch_bounds__(128) void attn_kernel(const __nv_bfloat16* __restrict__ qkv,
                                                   const float* __restrict__ abias,
                                                   __nv_bfloat16* __restrict__ out) {
    int blk = blockIdx.x;
    int w = blk / NH;
    int h = blk - w * NH;

    __shared__ __align__(16) __nv_bfloat16 sq[64 * 32];
    __shared__ __align__(16) __nv_bfloat16 sk[64 * 32];
    __shared__ __align__(16) __nv_bfloat16 sv[64 * 32];

    int tid = threadIdx.x;
    // fill q/k/v: 768 16B-chunks total
    {
        const __nv_bfloat16* base = qkv + (size_t)w * 64 * (3 * C) + h * HD;
        __nv_bfloat16* dsts[3] = { sq, sk, sv };
#pragma unroll
        for (int it = 0; it < 6; it++) {
            int idx = tid + it * 128;            // < 768
            int mat = idx >> 8;
            int r   = (idx >> 2) & 63;
            int c   = idx & 3;
            uint4 val = *(const uint4*)(base + (size_t)r * (3 * C) + mat * C + c * 8);
            *(uint4*)((char*)dsts[mat] + r * 64 + ((c ^ ((r >> 1) & 3)) << 4)) = val;
        }
    }
    __syncthreads();

    int warp = tid >> 5, lane = tid & 31;
    uint32_t sqb = (uint32_t)__cvta_generic_to_shared(sq);
    uint32_t skb = (uint32_t)__cvta_generic_to_shared(sk);
    uint32_t svb = (uint32_t)__cvta_generic_to_shared(sv);

    // ---- S = Q K^T ----
    float sacc[8][4];
#pragma unroll
    for (int i = 0; i < 8; i++)
#pragma unroll
        for (int q = 0; q < 4; q++) sacc[i][q] = 0.f;

    uint32_t qa[2][4];
#pragma unroll
    for (int ks = 0; ks < 2; ks++) {
        int row = warp * 16 + (lane & 7) + 8 * ((lane >> 3) & 1);
        int ch  = 2 * ks + (lane >> 4);
        ldsm_x4(qa[ks], sqb + row * 64 + ((ch ^ ((row >> 1) & 3)) << 4));
    }
#pragma unroll
    for (int ks = 0; ks < 2; ks++) {
#pragma unroll
        for (int np = 0; np < 4; np++) {
            int tok = np * 16 + (lane & 7) + 8 * (lane >> 4);
            int ch  = 2 * ks + ((lane >> 3) & 1);
            uint32_t kb[4];
            ldsm_x4(kb, skb + tok * 64 + ((ch ^ ((tok >> 1) & 3)) << 4));
            mma_bf16(sacc[2 * np],     qa[ks], kb);
            mma_bf16(sacc[2 * np + 1], qa[ks], kb + 2);
        }
    }

    // ---- bias + softmax (FMA-pipe exp) ----
    const float scale = 0.17677669529663687f;
    int q2 = (lane & 3) * 2;
    int r  = lane >> 2;
    int row0 = warp * 16 + r;
    const float* bt = abias + ((size_t)h * 64) * 64;
    float mx0 = -1e30f, mx1 = -1e30f;
#pragma unroll
    for (int nb = 0; nb < 8; nb++) {
        int mcol = nb * 8 + q2;
        const float* b0 = bt + row0 * 64 + mcol;
        const float* b1 = b0 + 8 * 64;
        sacc[nb][0] = fmaf(sacc[nb][0], scale, b0[0]);
        sacc[nb][1] = fmaf(sacc[nb][1], scale, b0[1]);
        sacc[nb][2] = fmaf(sacc[nb][2], scale, b1[0]);
        sacc[nb][3] = fmaf(sacc[nb][3], scale, b1[1]);
        mx0 = fmaxf(mx0, fmaxf(sacc[nb][0], sacc[nb][1]));
        mx1 = fmaxf(mx1, fmaxf(sacc[nb][2], sacc[nb][3]));
    }
#pragma unroll
    for (int o = 1; o < 4; o <<= 1) {
        mx0 = fmaxf(mx0, __shfl_xor_sync(0xffffffffu, mx0, o));
        mx1 = fmaxf(mx1, __shfl_xor_sync(0xffffffffu, mx1, o));
    }
    float sum0 = 0.f, sum1 = 0.f;
#pragma unroll
    for (int nb = 0; nb < 8; nb++) {
        sacc[nb][0] = fast_exp(sacc[nb][0] - mx0);
        sacc[nb][1] = fast_exp(sacc[nb][1] - mx0);
        sacc[nb][2] = fast_exp(sacc[nb][2] - mx1);
        sacc[nb][3] = fast_exp(sacc[nb][3] - mx1);
        sum0 += sacc[nb][0] + sacc[nb][1];
        sum1 += sacc[nb][2] + sacc[nb][3];
    }
#pragma unroll
    for (int o = 1; o < 4; o <<= 1) {
        sum0 += __shfl_xor_sync(0xffffffffu, sum0, o);
        sum1 += __shfl_xor_sync(0xffffffffu, sum1, o);
    }

    // pack P into A-fragments
    uint32_t pa[4][4];
#pragma unroll
    for (int ks = 0; ks < 4; ks++) {
        pa[ks][0] = packbf(sacc[2 * ks][0],     sacc[2 * ks][1]);
        pa[ks][1] = packbf(sacc[2 * ks][2],     sacc[2 * ks][3]);
        pa[ks][2] = packbf(sacc[2 * ks + 1][0], sacc[2 * ks + 1][1]);
        pa[ks][3] = packbf(sacc[2 * ks + 1][2], sacc[2 * ks + 1][3]);
    }

    // ---- O = P V ----
    float oacc[4][4];
#pragma unroll
    for (int i = 0; i < 4; i++)
#pragma unroll
        for (int q = 0; q < 4; q++) oacc[i][q] = 0.f;
#pragma unroll
    for (int ks = 0; ks < 4; ks++) {
#pragma unroll
        for (int np = 0; np < 2; np++) {
            int k  = ks * 16 + (lane & 7) + 8 * ((lane >> 3) & 1);
            int cn = np * 2 + (lane >> 4);
            uint32_t vb[4];
            ldsm_x4_t(vb, svb + k * 64 + ((cn ^ ((k >> 1) & 3)) << 4));
            mma_bf16(oacc[2 * np],     pa[ks], vb);
            mma_bf16(oacc[2 * np + 1], pa[ks], vb + 2);
        }
    }

    // ---- normalize + store ----
    float inv0 = 1.f / sum0, inv1 = 1.f / sum1;
    int tok0 = w * 64 + row0;
#pragma unroll
    for (int nb = 0; nb < 4; nb++) {
        int colh = nb * 8 + q2;
        __nv_bfloat16* o0 = out + (size_t)tok0 * C + h * HD + colh;
        __nv_bfloat16* o1 = o0 + 8 * C;
        *(uint32_t*)o0 = packbf(oacc[nb][0] * inv0, oacc[nb][1] * inv0);
        *(uint32_t*)o1 = packbf(oacc[nb][2] * inv1, oacc[nb][3] * inv1);
    }
}

// ---------------- launch ---------------------------------------------------
extern "C" void kernel_launch(void* const* d_in, const int* in_sizes, int n_in,
                              void* d_out, int out_size) {
    const float* x      = (const float*)d_in[0];
    const float* qkv_w  = (const float*)d_in[1];
    const float* qkv_b  = (const float*)d_in[2];
    const float* proj_w = (const float*)d_in[3];
    const float* proj_b = (const float*)d_in[4];
    const float* rpb    = (const float*)d_in[5];
    const float* n1s    = (const float*)d_in[6];
    const float* n1b    = (const float*)d_in[7];
    const float* n2s    = (const float*)d_in[8];
    const float* n2b    = (const float*)d_in[9];
    const float* w1     = (const float*)d_in[10];
    const float* b1     = (const float*)d_in[11];
    const float* w2     = (const float*)d_in[12];
    const float* b2     = (const float*)d_in[13];
    float* out = (float*)d_out;

    __nv_bfloat16 *xw, *qkv, *attn, *xn2, *h1, *wqkv, *wproj, *ww1, *ww2;
    float *x1, *abias;
    cudaGetSymbolAddress((void**)&xw,    g_xw);
    cudaGetSymbolAddress((void**)&qkv,   g_qkv);
    cudaGetSymbolAddress((void**)&attn,  g_attn);
    cudaGetSymbolAddress((void**)&x1,    g_x1);
    cudaGetSymbolAddress((void**)&xn2,   g_xn2);
    cudaGetSymbolAddress((void**)&h1,    g_h1);
    cudaGetSymbolAddress((void**)&wqkv,  g_wqkv);
    cudaGetSymbolAddress((void**)&wproj, g_wproj);
    cudaGetSymbolAddress((void**)&ww1,   g_w1);
    cudaGetSymbolAddress((void**)&ww2,   g_w2);
    cudaGetSymbolAddress((void**)&abias, g_abias);

    const int M = NTOK;

    // prep: bf16 weights + expanded attention bias table
    w2bf_kernel<<<(C * 3 * C + 255) / 256, 256>>>(qkv_w,  wqkv,  C * 3 * C);
    w2bf_kernel<<<(C * C + 255) / 256,     256>>>(proj_w, wproj, C * C);
    w2bf_kernel<<<(C * 4 * C + 255) / 256, 256>>>(w1,     ww1,   C * 4 * C);
    w2bf_kernel<<<(4 * C * C + 255) / 256, 256>>>(w2,     ww2,   4 * C * C);
    abias_kernel<<<(NH * 64 * 64 + 255) / 256, 256>>>(rpb, abias);

    // 1. LN1 + shift + window gather -> bf16
    ln_kernel<true><<<NTOK / 8, 256>>>(x, n1s, n1b, xw);

    // 2. QKV GEMM -> bf16
    bgemm<0><<<dim3((3 * C) / GBN, M / GBM), 256>>>(xw, wqkv, qkv_b,
                                                    nullptr, nullptr, qkv,
                                                    M, 3 * C, C);

    // 3. attention -> bf16
    attn_kernel<<<NWIN * NH, 128>>>(qkv, abias, attn);

    // 4. proj GEMM + scatter + residual -> fp32 x1
    bgemm<1><<<dim3(C / GBN, M / GBM), 256>>>(attn, wproj, proj_b,
                                              nullptr, x, x1,
                                              M, C, C);

    // 5. LN2 -> bf16
    ln_kernel<false><<<NTOK / 8, 256>>>(x1, n2s, n2b, xn2);

    // 6. MLP up + GELU -> bf16
    bgemm<2><<<dim3((4 * C) / GBN, M / GBM), 256>>>(xn2, ww1, b1,
                                                    nullptr, nullptr, h1,
                                                    M, 4 * C, C);

    // 7. MLP down + residual -> fp32 out
    bgemm<3><<<dim3(C / GBN, M / GBM), 256>>>(h1, ww2, b2,
                                              x1, nullptr, out,
                                              M, C, 4 * C);
}

// round 6
// speedup vs baseline: 5.5563x; 1.0281x over previous
#include <cuda_runtime.h>
#include <cuda_bf16.h>
#include <math.h>
#include <stdint.h>

// Problem constants
#define BATCH   8
#define HW      128
#define LTOK    16384
#define C       192
#define WS      8
#define SHIFT   4
#define NH      6
#define HD      32
#define NWIN    2048
#define NTOK    131072

// ---------------- scratch (device globals) ---------------------------------
__device__ __nv_bfloat16 g_xw  [(size_t)NTOK * C];
__device__ __nv_bfloat16 g_qkv [(size_t)NTOK * 3 * C];
__device__ float         g_x1  [(size_t)NTOK * C];
__device__ __nv_bfloat16 g_xn2 [(size_t)NTOK * C];
__device__ __nv_bfloat16 g_wqkv [C * 3 * C];    // [K,N] bf16
__device__ __nv_bfloat16 g_wproj[C * C];        // [K,N] bf16
__device__ __nv_bfloat16 g_w1   [C * 4 * C];    // [K,N] bf16
__device__ __nv_bfloat16 g_w2   [4 * C * C];    // [K,N] bf16
__device__ float         g_abias[NH * 64 * 64];

// ---------------- helpers --------------------------------------------------
__device__ __forceinline__ uint32_t smem_u32(const void* p) {
    return (uint32_t)__cvta_generic_to_shared(p);
}
__device__ __forceinline__ void cpasync16(uint32_t dst, const void* src) {
    asm volatile("cp.async.cg.shared.global [%0], [%1], 16;" :: "r"(dst), "l"(src));
}
__device__ __forceinline__ void ldsm_x4(uint32_t* r, uint32_t addr) {
    asm volatile("ldmatrix.sync.aligned.m8n8.x4.shared.b16 {%0,%1,%2,%3}, [%4];"
        : "=r"(r[0]), "=r"(r[1]), "=r"(r[2]), "=r"(r[3]) : "r"(addr));
}
__device__ __forceinline__ void ldsm_x4_t(uint32_t* r, uint32_t addr) {
    asm volatile("ldmatrix.sync.aligned.m8n8.x4.trans.shared.b16 {%0,%1,%2,%3}, [%4];"
        : "=r"(r[0]), "=r"(r[1]), "=r"(r[2]), "=r"(r[3]) : "r"(addr));
}
__device__ __forceinline__ void mma_bf16(float* d, const uint32_t* a, const uint32_t* b) {
    asm volatile(
        "mma.sync.aligned.m16n8k16.row.col.f32.bf16.bf16.f32 "
        "{%0,%1,%2,%3}, {%4,%5,%6,%7}, {%8,%9}, {%0,%1,%2,%3};"
        : "+f"(d[0]), "+f"(d[1]), "+f"(d[2]), "+f"(d[3])
        : "r"(a[0]), "r"(a[1]), "r"(a[2]), "r"(a[3]), "r"(b[0]), "r"(b[1]));
}
__device__ __forceinline__ uint32_t packbf(float lo, float hi) {
    uint32_t r;
    asm("cvt.rn.bf16x2.f32 %0, %1, %2;" : "=r"(r) : "f"(hi), "f"(lo));
    return r;
}
__device__ __forceinline__ float fast_exp(float x) {
    float t = fmaxf(x * 1.4426950408889634f, -100.f);
    float z = t + 12582912.f;
    int   ni = __float_as_int(z);
    float nf = z - 12582912.f;
    float f  = t - nf;
    float p = 1.33335581e-3f;
    p = fmaf(p, f, 9.61812910e-3f);
    p = fmaf(p, f, 5.55041087e-2f);
    p = fmaf(p, f, 2.40226507e-1f);
    p = fmaf(p, f, 6.93147181e-1f);
    p = fmaf(p, f, 1.0f);
    float sc = __int_as_float((((ni & 0x7FFFFF) - 0x400000) + 127) << 23);
    return p * sc;
}

// window-row (w*64+n) -> flat token index
__device__ __forceinline__ int win_row_to_tok(int row) {
    int w  = row >> 6;
    int n  = row & 63;
    int b  = w >> 8;
    int wy = (w >> 4) & 15;
    int wx = w & 15;
    int iy = n >> 3;
    int ix = n & 7;
    int hr = (wy * WS + iy + SHIFT) & (HW - 1);
    int wr = (wx * WS + ix + SHIFT) & (HW - 1);
    return (b << 14) + (hr << 7) + wr;
}

// ---------------- prep kernels ---------------------------------------------
__global__ void w2bf_kernel(const float* __restrict__ in, __nv_bfloat16* __restrict__ out, int n) {
    int i = blockIdx.x * 256 + threadIdx.x;
    if (i < n) out[i] = __float2bfloat16(in[i]);
}
__global__ void abias_kernel(const float* __restrict__ rpb, float* __restrict__ tab) {
    int i = blockIdx.x * 256 + threadIdx.x;
    if (i >= NH * 64 * 64) return;
    int h = i >> 12;
    int n = (i >> 6) & 63;
    int m = i & 63;
    int iy = n >> 3, ix = n & 7, jy = m >> 3, jx = m & 7;
    int ridx = (iy - jy + 7) * 15 + (ix - jx + 7);
    tab[i] = rpb[ridx * NH + h];
}

// ---------------- LayerNorm1 (gathered) -> bf16 window order ---------------
__global__ __launch_bounds__(256) void ln_kernel(const float* __restrict__ x,
                                                 const float* __restrict__ s,
                                                 const float* __restrict__ b,
                                                 __nv_bfloat16* __restrict__ out) {
    int warp = threadIdx.x >> 5;
    int lane = threadIdx.x & 31;
    int row  = blockIdx.x * 8 + warp;
    int src  = win_row_to_tok(row);
    const float* xp = x + (size_t)src * C;

    float v[6];
    float sum = 0.f, sq = 0.f;
#pragma unroll
    for (int i = 0; i < 6; i++) {
        v[i] = xp[lane + i * 32];
        sum += v[i];
        sq  += v[i] * v[i];
    }
#pragma unroll
    for (int o = 16; o > 0; o >>= 1) {
        sum += __shfl_xor_sync(0xffffffffu, sum, o);
        sq  += __shfl_xor_sync(0xffffffffu, sq, o);
    }
    float mean = sum * (1.f / C);
    float var  = sq * (1.f / C) - mean * mean;
    float rstd = rsqrtf(var + 1e-5f);

    __nv_bfloat16* op = out + (size_t)row * C;
#pragma unroll
    for (int i = 0; i < 6; i++) {
        int c = lane + i * 32;
        op[c] = __float2bfloat16((v[i] - mean) * rstd * s[c] + b[c]);
    }
}

// ---------------- bf16 MMA GEMM for QKV (R3-proven) ------------------------
#define GBM 256
#define GBN 64
#define GBK 32

__global__ __launch_bounds__(256, 2) void qkv_gemm(const __nv_bfloat16* __restrict__ A,
                                                   const __nv_bfloat16* __restrict__ Bm,
                                                   const float* __restrict__ bias,
                                                   __nv_bfloat16* __restrict__ out,
                                                   int M, int N, int K) {
    __shared__ __align__(16) __nv_bfloat16 As[2][GBM * GBK];
    __shared__ __align__(16) __nv_bfloat16 Bs[2][GBK * GBN];

    int tid  = threadIdx.x;
    int wid  = tid >> 5, lane = tid & 31;
    int wm   = (wid & 3) * 64;
    int wn   = (wid >> 2) * 32;
    int m0   = blockIdx.y * GBM;
    int n0   = blockIdx.x * GBN;

    uint32_t sa = smem_u32(&As[0][0]);
    uint32_t sb = smem_u32(&Bs[0][0]);

    uint32_t aoff[4][2], boff[2][2];
#pragma unroll
    for (int ma = 0; ma < 4; ma++)
#pragma unroll
        for (int ks = 0; ks < 2; ks++) {
            int row = wm + ma * 16 + (lane & 7) + 8 * ((lane >> 3) & 1);
            int ch  = 2 * ks + (lane >> 4);
            aoff[ma][ks] = row * 64 + ((ch ^ ((row >> 1) & 3)) << 4);
        }
#pragma unroll
    for (int np = 0; np < 2; np++)
#pragma unroll
        for (int ks = 0; ks < 2; ks++) {
            int k  = ks * 16 + (lane & 7) + 8 * ((lane >> 3) & 1);
            int cn = (wn >> 3) + np * 2 + (lane >> 4);
            boff[np][ks] = k * 128 + ((cn ^ (k & 7)) << 4);
        }

    float acc[4][4][4];
#pragma unroll
    for (int i = 0; i < 4; i++)
#pragma unroll
        for (int j = 0; j < 4; j++)
#pragma unroll
            for (int q = 0; q < 4; q++) acc[i][j][q] = 0.f;

    const int nk = K / GBK;
    int arow = tid >> 2, ac = tid & 3;
    int bk = tid >> 3,  bcn = tid & 7;
    uint32_t adst0 = arow * 64 + ((ac ^ ((arow >> 1) & 3)) << 4);
    uint32_t bdst  = bk * 128 + ((bcn ^ (bk & 7)) << 4);

    auto issue = [&](int kt, int buf) {
        const __nv_bfloat16* ga = A + (size_t)m0 * K + kt * GBK + ac * 8;
#pragma unroll
        for (int p = 0; p < 4; p++) {
            int row = arow + p * 64;
            cpasync16(sa + buf * (GBM * GBK * 2) + adst0 + p * (64 * 64),
                      ga + (size_t)row * K);
        }
        cpasync16(sb + buf * (GBK * GBN * 2) + bdst,
                  Bm + (size_t)(kt * GBK + bk) * N + n0 + bcn * 8);
        asm volatile("cp.async.commit_group;" ::: "memory");
    };

    issue(0, 0);
    int buf = 0;
    for (int kt = 0; kt < nk; kt++) {
        if (kt + 1 < nk) {
            issue(kt + 1, buf ^ 1);
            asm volatile("cp.async.wait_group 1;" ::: "memory");
        } else {
            asm volatile("cp.async.wait_group 0;" ::: "memory");
        }
        __syncthreads();

        uint32_t ab = sa + buf * (GBM * GBK * 2);
        uint32_t bb = sb + buf * (GBK * GBN * 2);
#pragma unroll
        for (int ks = 0; ks < 2; ks++) {
            uint32_t af[4][4], bfr[4][2];
#pragma unroll
            for (int ma = 0; ma < 4; ma++) ldsm_x4(af[ma], ab + aoff[ma][ks]);
#pragma unroll
            for (int np = 0; np < 2; np++) {
                uint32_t t4[4];
                ldsm_x4_t(t4, bb + boff[np][ks]);
                bfr[np * 2][0] = t4[0]; bfr[np * 2][1] = t4[1];
                bfr[np * 2 + 1][0] = t4[2]; bfr[np * 2 + 1][1] = t4[3];
            }
#pragma unroll
            for (int ma = 0; ma < 4; ma++)
#pragma unroll
                for (int nb = 0; nb < 4; nb++)
                    mma_bf16(acc[ma][nb], af[ma], bfr[nb]);
        }
        __syncthreads();
        buf ^= 1;
    }

    int g = lane >> 2, tig = lane & 3;
#pragma unroll
    for (int ma = 0; ma < 4; ma++) {
        int rlo = m0 + wm + ma * 16 + g;
        int rhi = rlo + 8;
#pragma unroll
        for (int nb = 0; nb < 4; nb++) {
            int col = n0 + wn + nb * 8 + tig * 2;
            float bi0 = bias[col], bi1 = bias[col + 1];
            *(uint32_t*)&out[(size_t)rlo * N + col] = packbf(acc[ma][nb][0] + bi0, acc[ma][nb][1] + bi1);
            *(uint32_t*)&out[(size_t)rhi * N + col] = packbf(acc[ma][nb][2] + bi0, acc[ma][nb][3] + bi1);
        }
    }
}

// ---------------- megakernel: attention + proj + residual + LN2 ------------
// CTA = 2 windows = 128 rows. smem layout (bytes):
//   [0, 24576)        sqkv: 3 mats x 2 wins x (64 rows x 64B)
//   [24576, 73728)    sA: attention output 128 x 192 bf16 (384B rows, swizzled)
//   [73728, 147456)   sW: Wproj 192 x 192 bf16 (384B rows, swizzled)
//   sOut (fp32 128 x 196) overlays [24576, 124928) after GEMM.
#define MK_SMEM 147456
#define LNW 196

__global__ __launch_bounds__(256) void attnproj_kernel(const __nv_bfloat16* __restrict__ qkv,
                                                       const float* __restrict__ abias,
                                                       const __nv_bfloat16* __restrict__ wproj,
                                                       const float* __restrict__ pbias,
                                                       const float* __restrict__ x,
                                                       const float* __restrict__ n2s,
                                                       const float* __restrict__ n2b,
                                                       float* __restrict__ x1,
                                                       __nv_bfloat16* __restrict__ xn2) {
    extern __shared__ char sm[];
    char* sA_p = sm + 24576;
    char* sW_p = sm + 73728;
    float* sOut = (float*)(sm + 24576);

    int tid  = threadIdx.x;
    int wid  = tid >> 5, lane = tid & 31;
    int m0   = blockIdx.x * 128;

    uint32_t sqkvb = smem_u32(sm);
    uint32_t sab   = smem_u32(sA_p);
    uint32_t swb   = smem_u32(sW_p);

    // stage Wproj (4608 16B chunks)
#pragma unroll
    for (int j = 0; j < 18; j++) {
        int i = tid + j * 256;
        int r = i / 24, cch = i % 24;
        cpasync16(swb + r * 384 + ((cch ^ (r & 7)) << 4), wproj + (size_t)r * 192 + cch * 8);
    }
    asm volatile("cp.async.commit_group;" ::: "memory");

    int win = wid >> 2, w4 = wid & 3;
    int g = lane >> 2, q2 = (lane & 3) * 2;

    // ---------- per-head attention ----------
    for (int hh = 0; hh < NH; hh++) {
        // load q/k/v for both windows, this head (1536 16B chunks)
#pragma unroll
        for (int it = 0; it < 6; it++) {
            int idx = tid + it * 256;
            int mat = idx / 512;
            int rem = idx & 511;
            int wn_ = rem >> 8;
            int r   = (rem >> 2) & 63;
            int c   = rem & 3;
            uint4 val = *(const uint4*)(qkv + (size_t)(m0 + wn_ * 64 + r) * 576 + mat * 192 + hh * 32 + c * 8);
            *(uint4*)(sm + mat * 8192 + wn_ * 4096 + r * 64 + ((c ^ ((r >> 1) & 3)) << 4)) = val;
        }
        __syncthreads();

        uint32_t sqb = sqkvb + win * 4096;
        uint32_t skb = sqkvb + 8192 + win * 4096;
        uint32_t svb = sqkvb + 16384 + win * 4096;

        float sacc[8][4];
#pragma unroll
        for (int i = 0; i < 8; i++)
#pragma unroll
            for (int q = 0; q < 4; q++) sacc[i][q] = 0.f;

        uint32_t qa[2][4];
#pragma unroll
        for (int ks = 0; ks < 2; ks++) {
            int row = w4 * 16 + (lane & 7) + 8 * ((lane >> 3) & 1);
            int ch  = 2 * ks + (lane >> 4);
            ldsm_x4(qa[ks], sqb + row * 64 + ((ch ^ ((row >> 1) & 3)) << 4));
        }
#pragma unroll
        for (int ks = 0; ks < 2; ks++) {
#pragma unroll
            for (int np = 0; np < 4; np++) {
                int tok = np * 16 + (lane & 7) + 8 * (lane >> 4);
                int ch  = 2 * ks + ((lane >> 3) & 1);
                uint32_t kb[4];
                ldsm_x4(kb, skb + tok * 64 + ((ch ^ ((tok >> 1) & 3)) << 4));
                mma_bf16(sacc[2 * np],     qa[ks], kb);
                mma_bf16(sacc[2 * np + 1], qa[ks], kb + 2);
            }
        }

        const float scale = 0.17677669529663687f;
        int row0 = w4 * 16 + g;
        const float* bt = abias + ((size_t)hh * 64) * 64;
        float mx0 = -1e30f, mx1 = -1e30f;
#pragma unroll
        for (int nb = 0; nb < 8; nb++) {
            int mcol = nb * 8 + q2;
            const float* b0 = bt + row0 * 64 + mcol;
            const float* b1 = b0 + 8 * 64;
            sacc[nb][0] = fmaf(sacc[nb][0], scale, b0[0]);
            sacc[nb][1] = fmaf(sacc[nb][1], scale, b0[1]);
            sacc[nb][2] = fmaf(sacc[nb][2], scale, b1[0]);
            sacc[nb][3] = fmaf(sacc[nb][3], scale, b1[1]);
            mx0 = fmaxf(mx0, fmaxf(sacc[nb][0], sacc[nb][1]));
            mx1 = fmaxf(mx1, fmaxf(sacc[nb][2], sacc[nb][3]));
        }
#pragma unroll
        for (int o = 1; o < 4; o <<= 1) {
            mx0 = fmaxf(mx0, __shfl_xor_sync(0xffffffffu, mx0, o));
            mx1 = fmaxf(mx1, __shfl_xor_sync(0xffffffffu, mx1, o));
        }
        float sum0 = 0.f, sum1 = 0.f;
#pragma unroll
        for (int nb = 0; nb < 8; nb++) {
            sacc[nb][0] = fast_exp(sacc[nb][0] - mx0);
            sacc[nb][1] = fast_exp(sacc[nb][1] - mx0);
            sacc[nb][2] = fast_exp(sacc[nb][2] - mx1);
            sacc[nb][3] = fast_exp(sacc[nb][3] - mx1);
            sum0 += sacc[nb][0] + sacc[nb][1];
            sum1 += sacc[nb][2] + sacc[nb][3];
        }
#pragma unroll
        for (int o = 1; o < 4; o <<= 1) {
            sum0 += __shfl_xor_sync(0xffffffffu, sum0, o);
            sum1 += __shfl_xor_sync(0xffffffffu, sum1, o);
        }

        uint32_t pa[4][4];
#pragma unroll
        for (int ks = 0; ks < 4; ks++) {
            pa[ks][0] = packbf(sacc[2 * ks][0],     sacc[2 * ks][1]);
            pa[ks][1] = packbf(sacc[2 * ks][2],     sacc[2 * ks][3]);
            pa[ks][2] = packbf(sacc[2 * ks + 1][0], sacc[2 * ks + 1][1]);
            pa[ks][3] = packbf(sacc[2 * ks + 1][2], sacc[2 * ks + 1][3]);
        }

        float oacc[4][4];
#pragma unroll
        for (int i = 0; i < 4; i++)
#pragma unroll
            for (int q = 0; q < 4; q++) oacc[i][q] = 0.f;
#pragma unroll
        for (int ks = 0; ks < 4; ks++) {
#pragma unroll
            for (int np = 0; np < 2; np++) {
                int k  = ks * 16 + (lane & 7) + 8 * ((lane >> 3) & 1);
                int cn = np * 2 + (lane >> 4);
                uint32_t vb[4];
                ldsm_x4_t(vb, svb + k * 64 + ((cn ^ ((k >> 1) & 3)) << 4));
                mma_bf16(oacc[2 * np],     pa[ks], vb);
                mma_bf16(oacc[2 * np + 1], pa[ks], vb + 2);
            }
        }

        // store normalized P*V into sA (swizzled 384B rows)
        float inv0 = 1.f / sum0, inv1 = 1.f / sum1;
        int rl = win * 64 + row0;
        int rh = rl + 8;
#pragma unroll
        for (int nb = 0; nb < 4; nb++) {
            int chA = hh * 4 + nb;
            *(uint32_t*)(sA_p + rl * 384 + ((chA ^ (rl & 7)) << 4) + q2 * 2) =
                packbf(oacc[nb][0] * inv0, oacc[nb][1] * inv0);
            *(uint32_t*)(sA_p + rh * 384 + ((chA ^ (rh & 7)) << 4) + q2 * 2) =
                packbf(oacc[nb][2] * inv1, oacc[nb][3] * inv1);
        }
        __syncthreads();
    }

    asm volatile("cp.async.wait_group 0;" ::: "memory");
    __syncthreads();

    // ---------- proj GEMM: [128x192] = sA[128x192] @ sW[192x192] ----------
    int wm = (wid & 3) * 32;
    int wn = (wid >> 2) * 96;
    float acc[2][12][4];
#pragma unroll
    for (int i = 0; i < 2; i++)
#pragma unroll
        for (int j = 0; j < 12; j++)
#pragma unroll
            for (int q = 0; q < 4; q++) acc[i][j][q] = 0.f;

#pragma unroll
    for (int kk = 0; kk < 12; kk++) {
        uint32_t af[2][4];
#pragma unroll
        for (int fi = 0; fi < 2; fi++) {
            int row = wm + fi * 16 + (lane & 7) + 8 * ((lane >> 3) & 1);
            int ch  = 2 * kk + (lane >> 4);
            ldsm_x4(af[fi], sab + row * 384 + ((ch ^ (row & 7)) << 4));
        }
        uint32_t bfr[12][2];
#pragma unroll
        for (int j = 0; j < 6; j++) {
            int k  = kk * 16 + (lane & 7) + 8 * ((lane >> 3) & 1);
            int cn = (wn >> 3) + 2 * j + (lane >> 4);
            uint32_t t4[4];
            ldsm_x4_t(t4, swb + k * 384 + ((cn ^ (k & 7)) << 4));
            bfr[2 * j][0] = t4[0]; bfr[2 * j][1] = t4[1];
            bfr[2 * j + 1][0] = t4[2]; bfr[2 * j + 1][1] = t4[3];
        }
#pragma unroll
        for (int fi = 0; fi < 2; fi++)
#pragma unroll
            for (int nj = 0; nj < 12; nj++)
                mma_bf16(acc[fi][nj], af[fi], bfr[nj]);
    }
    __syncthreads();   // sA/sW reads done; safe to overlay sOut

    // epilogue: + bias + gathered residual -> sOut (fp32)
#pragma unroll
    for (int fi = 0; fi < 2; fi++) {
        int rl = wm + fi * 16 + g;
        int rh = rl + 8;
        int tokl = win_row_to_tok(m0 + rl);
        int tokh = win_row_to_tok(m0 + rh);
#pragma unroll
        for (int nj = 0; nj < 12; nj++) {
            int col = wn + nj * 8 + q2;
            float bi0 = pbias[col], bi1 = pbias[col + 1];
            float2 xl = *(const float2*)&x[(size_t)tokl * C + col];
            float2 xh = *(const float2*)&x[(size_t)tokh * C + col];
            sOut[rl * LNW + col]     = acc[fi][nj][0] + bi0 + xl.x;
            sOut[rl * LNW + col + 1] = acc[fi][nj][1] + bi1 + xl.y;
            sOut[rh * LNW + col]     = acc[fi][nj][2] + bi0 + xh.x;
            sOut[rh * LNW + col + 1] = acc[fi][nj][3] + bi1 + xh.y;
        }
    }
    __syncthreads();

    // LN2 per row (warp wid handles rows wid*16 .. +15), write x1 + xn2
#pragma unroll
    for (int rr = 0; rr < 16; rr++) {
        int row = wid * 16 + rr;
        const float* rp = sOut + row * LNW;
        float v[6];
        float sum = 0.f, sq = 0.f;
#pragma unroll
        for (int i = 0; i < 6; i++) {
            v[i] = rp[lane + i * 32];
            sum += v[i];
            sq  += v[i] * v[i];
        }
#pragma unroll
        for (int o = 16; o > 0; o >>= 1) {
            sum += __shfl_xor_sync(0xffffffffu, sum, o);
            sq  += __shfl_xor_sync(0xffffffffu, sq, o);
        }
        float mean = sum * (1.f / C);
        float var  = sq * (1.f / C) - mean * mean;
        float rstd = rsqrtf(var + 1e-5f);

        int tok = win_row_to_tok(m0 + row);
        float* x1p = x1 + (size_t)tok * C;
        __nv_bfloat16* xnp = xn2 + (size_t)tok * C;
#pragma unroll
        for (int i = 0; i < 6; i++) {
            int c = lane + i * 32;
            x1p[c] = v[i];
            xnp[c] = __float2bfloat16((v[i] - mean) * rstd * n2s[c] + n2b[c]);
        }
    }
}

// ---------------- fused MLP: out = gelu(xn2@W1+b1)@W2 + b2 + x1 ------------
// CTA = 64 rows. hidden chunked 4 x 192, h lives in smem only.
// smem: sXn [0,24576) ; sH [24576,49152) ; sB 2 x 12288 at [49152,73728)
#define MLP_SMEM 73728

__device__ __forceinline__ void mlp_gemm_inner(uint32_t aBase, uint32_t sbBase,
                                               const __nv_bfloat16* __restrict__ Wg,
                                               int rstride, int rowbase, int coloff,
                                               int wm, int wn, int tid, int lane,
                                               float acc[2][6][4]) {
    auto issueW = [&](int s, int buf) {
#pragma unroll
        for (int j = 0; j < 3; j++) {
            int i = tid + j * 256;
            int kl = i / 24, cch = i % 24;
            cpasync16(sbBase + buf * 12288 + kl * 384 + ((cch ^ (kl & 7)) << 4),
                      Wg + (size_t)(rowbase + s * 32 + kl) * rstride + coloff + cch * 8);
        }
        asm volatile("cp.async.commit_group;" ::: "memory");
    };

    issueW(0, 0);
    for (int s = 0; s < 6; s++) {
        if (s < 5) {
            issueW(s + 1, (s + 1) & 1);
            asm volatile("cp.async.wait_group 1;" ::: "memory");
        } else {
            asm volatile("cp.async.wait_group 0;" ::: "memory");
        }
        __syncthreads();
        uint32_t bb = sbBase + (s & 1) * 12288;
#pragma unroll
        for (int t = 0; t < 2; t++) {
            int kk = s * 2 + t;
            uint32_t af[2][4];
#pragma unroll
            for (int fi = 0; fi < 2; fi++) {
                int row = wm + fi * 16 + (lane & 7) + 8 * ((lane >> 3) & 1);
                int ch  = 2 * kk + (lane >> 4);
                ldsm_x4(af[fi], aBase + row * 384 + ((ch ^ (row & 7)) << 4));
            }
            uint32_t bfr[6][2];
#pragma unroll
            for (int j = 0; j < 3; j++) {
                int kl = t * 16 + (lane & 7) + 8 * ((lane >> 3) & 1);
                int cn = (wn >> 3) + 2 * j + (lane >> 4);
                uint32_t t4[4];
                ldsm_x4_t(t4, bb + kl * 384 + ((cn ^ (kl & 7)) << 4));
                bfr[2 * j][0] = t4[0]; bfr[2 * j][1] = t4[1];
                bfr[2 * j + 1][0] = t4[2]; bfr[2 * j + 1][1] = t4[3];
            }
#pragma unroll
            for (int fi = 0; fi < 2; fi++)
#pragma unroll
                for (int nj = 0; nj < 6; nj++)
                    mma_bf16(acc[fi][nj], af[fi], bfr[nj]);
        }
        __syncthreads();
    }
}

__global__ __launch_bounds__(256) void mlp_kernel(const __nv_bfloat16* __restrict__ xn,
                                                  const __nv_bfloat16* __restrict__ w1,
                                                  const float* __restrict__ b1,
                                                  const __nv_bfloat16* __restrict__ w2,
                                                  const float* __restrict__ b2,
                                                  const float* __restrict__ x1,
                                                  float* __restrict__ out) {
    extern __shared__ char sm[];
    char* sH_p = sm + 24576;
    uint32_t sxn = smem_u32(sm);
    uint32_t shb = sxn + 24576;
    uint32_t sbb = sxn + 49152;

    int tid = threadIdx.x;
    int wid = tid >> 5, lane = tid & 31;
    int m0 = blockIdx.x * 64;
    int wm = (wid & 1) * 32;
    int wn = (wid >> 1) * 48;
    int g = lane >> 2, q2 = (lane & 3) * 2;

    // load xn tile (1536 16B chunks)
#pragma unroll
    for (int j = 0; j < 6; j++) {
        int i = tid + j * 256;
        int r = i / 24, cch = i % 24;
        cpasync16(sxn + r * 384 + ((cch ^ (r & 7)) << 4), xn + (size_t)(m0 + r) * C + cch * 8);
    }
    asm volatile("cp.async.commit_group;" ::: "memory");
    asm volatile("cp.async.wait_group 0;" ::: "memory");
    __syncthreads();

    float acc2[2][6][4];
#pragma unroll
    for (int i = 0; i < 2; i++)
#pragma unroll
        for (int j = 0; j < 6; j++)
#pragma unroll
            for (int q = 0; q < 4; q++) acc2[i][j][q] = 0.f;

    for (int c = 0; c < 4; c++) {
        // GEMM1: h = xn @ W1[:, c*192 .. +191]
        float acc1[2][6][4];
#pragma unroll
        for (int i = 0; i < 2; i++)
#pragma unroll
            for (int j = 0; j < 6; j++)
#pragma unroll
                for (int q = 0; q < 4; q++) acc1[i][j][q] = 0.f;
        mlp_gemm_inner(sxn, sbb, w1, 4 * C, 0, c * 192, wm, wn, tid, lane, acc1);

        // bias + GELU -> sH
        const float is2 = 0.70710678118654752f;
#pragma unroll
        for (int fi = 0; fi < 2; fi++) {
            int rl = wm + fi * 16 + g;
            int rh = rl + 8;
#pragma unroll
            for (int nj = 0; nj < 6; nj++) {
                int colL = wn + nj * 8 + q2;
                int gcol = c * 192 + colL;
                float bi0 = b1[gcol], bi1 = b1[gcol + 1];
                float v00 = acc1[fi][nj][0] + bi0;
                float v01 = acc1[fi][nj][1] + bi1;
                float v10 = acc1[fi][nj][2] + bi0;
                float v11 = acc1[fi][nj][3] + bi1;
                v00 = 0.5f * v00 * (1.f + erff(v00 * is2));
                v01 = 0.5f * v01 * (1.f + erff(v01 * is2));
                v10 = 0.5f * v10 * (1.f + erff(v10 * is2));
                v11 = 0.5f * v11 * (1.f + erff(v11 * is2));
                int chh = colL >> 3;
                *(uint32_t*)(sH_p + rl * 384 + ((chh ^ (rl & 7)) << 4) + q2 * 2) = packbf(v00, v01);
                *(uint32_t*)(sH_p + rh * 384 + ((chh ^ (rh & 7)) << 4) + q2 * 2) = packbf(v10, v11);
            }
        }
        __syncthreads();

        // GEMM2: out += h @ W2[c*192 .. +191, :]
        mlp_gemm_inner(shb, sbb, w2, C, c * 192, 0, wm, wn, tid, lane, acc2);
    }

    // epilogue: + b2 + x1 residual -> fp32 out
#pragma unroll
    for (int fi = 0; fi < 2; fi++) {
        int ml = m0 + wm + fi * 16 + g;
        int mh = ml + 8;
#pragma unroll
        for (int nj = 0; nj < 6; nj++) {
            int col = wn + nj * 8 + q2;
            float bi0 = b2[col], bi1 = b2[col + 1];
            float2 xl = *(const float2*)&x1[(size_t)ml * C + col];
            float2 xh = *(const float2*)&x1[(size_t)mh * C + col];
            *(float2*)&out[(size_t)ml * C + col] =
                make_float2(acc2[fi][nj][0] + bi0 + xl.x, acc2[fi][nj][1] + bi1 + xl.y);
            *(float2*)&out[(size_t)mh * C + col] =
                make_float2(acc2[fi][nj][2] + bi0 + xh.x, acc2[fi][nj][3] + bi1 + xh.y);
        }
    }
}

// ---------------- launch ---------------------------------------------------
extern "C" void kernel_launch(void* const* d_in, const int* in_sizes, int n_in,
                              void* d_out, int out_size) {
    const float* x      = (const float*)d_in[0];
    const float* qkv_w  = (const float*)d_in[1];
    const float* qkv_b  = (const float*)d_in[2];
    const float* proj_w = (const float*)d_in[3];
    const float* proj_b = (const float*)d_in[4];
    const float* rpb    = (const float*)d_in[5];
    const float* n1s    = (const float*)d_in[6];
    const float* n1b    = (const float*)d_in[7];
    const float* n2s    = (const float*)d_in[8];
    const float* n2b    = (const float*)d_in[9];
    const float* w1     = (const float*)d_in[10];
    const float* b1     = (const float*)d_in[11];
    const float* w2     = (const float*)d_in[12];
    const float* b2     = (const float*)d_in[13];
    float* out = (float*)d_out;

    __nv_bfloat16 *xw, *qkv, *xn2, *wqkv, *wproj, *ww1, *ww2;
    float *x1, *abias;
    cudaGetSymbolAddress((void**)&xw,    g_xw);
    cudaGetSymbolAddress((void**)&qkv,   g_qkv);
    cudaGetSymbolAddress((void**)&x1,    g_x1);
    cudaGetSymbolAddress((void**)&xn2,   g_xn2);
    cudaGetSymbolAddress((void**)&wqkv,  g_wqkv);
    cudaGetSymbolAddress((void**)&wproj, g_wproj);
    cudaGetSymbolAddress((void**)&ww1,   g_w1);
    cudaGetSymbolAddress((void**)&ww2,   g_w2);
    cudaGetSymbolAddress((void**)&abias, g_abias);

    cudaFuncSetAttribute(attnproj_kernel, cudaFuncAttributeMaxDynamicSharedMemorySize, MK_SMEM);
    cudaFuncSetAttribute(mlp_kernel,      cudaFuncAttributeMaxDynamicSharedMemorySize, MLP_SMEM);

    // prep: bf16 weights (straight [K,N]) + attention bias table
    w2bf_kernel<<<(C * 3 * C + 255) / 256, 256>>>(qkv_w,  wqkv,  C * 3 * C);
    w2bf_kernel<<<(C * C + 255) / 256,     256>>>(proj_w, wproj, C * C);
    w2bf_kernel<<<(C * 4 * C + 255) / 256, 256>>>(w1,     ww1,   C * 4 * C);
    w2bf_kernel<<<(4 * C * C + 255) / 256, 256>>>(w2,     ww2,   4 * C * C);
    abias_kernel<<<(NH * 64 * 64 + 255) / 256, 256>>>(rpb, abias);

    // 1. LN1 + shift + window gather -> bf16
    ln_kernel<<<NTOK / 8, 256>>>(x, n1s, n1b, xw);

    // 2. QKV GEMM -> bf16
    qkv_gemm<<<dim3((3 * C) / GBN, NTOK / GBM), 256>>>(xw, wqkv, qkv_b, qkv,
                                                       NTOK, 3 * C, C);

    // 3. attention + proj + residual + LN2 -> x1 (fp32) & xn2 (bf16), token order
    attnproj_kernel<<<NTOK / 128, 256, MK_SMEM>>>(qkv, abias, wproj, proj_b,
                                                  x, n2s, n2b, x1, xn2);

    // 4. fused MLP + residual -> out
    mlp_kernel<<<NTOK / 64, 256, MLP_SMEM>>>(xn2, ww1, b1, ww2, b2, x1, out);
}

// round 7
// speedup vs baseline: 5.5749x; 1.0033x over previous
#include <cuda_runtime.h>
#include <cuda_bf16.h>
#include <math.h>
#include <stdint.h>

// Problem constants
#define BATCH   8
#define HW      128
#define LTOK    16384
#define C       192
#define WS      8
#define SHIFT   4
#define NH      6
#define HD      32
#define NWIN    2048
#define NTOK    131072

// ---------------- scratch (device globals) ---------------------------------
__device__ __nv_bfloat16 g_xw  [(size_t)NTOK * C];
__device__ __nv_bfloat16 g_qkv [(size_t)NTOK * 3 * C];
__device__ float         g_x1  [(size_t)NTOK * C];
__device__ __nv_bfloat16 g_xn2 [(size_t)NTOK * C];
__device__ __nv_bfloat16 g_wqkv [C * 3 * C];    // [K,N] bf16
__device__ __nv_bfloat16 g_wproj[C * C];        // [K,N] bf16
__device__ __nv_bfloat16 g_w1   [C * 4 * C];    // [K,N] bf16
__device__ __nv_bfloat16 g_w2   [4 * C * C];    // [K,N] bf16
__device__ float         g_abias[NH * 64 * 64];

// ---------------- helpers --------------------------------------------------
__device__ __forceinline__ uint32_t smem_u32(const void* p) {
    return (uint32_t)__cvta_generic_to_shared(p);
}
__device__ __forceinline__ void cpasync16(uint32_t dst, const void* src) {
    asm volatile("cp.async.cg.shared.global [%0], [%1], 16;" :: "r"(dst), "l"(src));
}
__device__ __forceinline__ void ldsm_x4(uint32_t* r, uint32_t addr) {
    asm volatile("ldmatrix.sync.aligned.m8n8.x4.shared.b16 {%0,%1,%2,%3}, [%4];"
        : "=r"(r[0]), "=r"(r[1]), "=r"(r[2]), "=r"(r[3]) : "r"(addr));
}
__device__ __forceinline__ void ldsm_x4_t(uint32_t* r, uint32_t addr) {
    asm volatile("ldmatrix.sync.aligned.m8n8.x4.trans.shared.b16 {%0,%1,%2,%3}, [%4];"
        : "=r"(r[0]), "=r"(r[1]), "=r"(r[2]), "=r"(r[3]) : "r"(addr));
}
__device__ __forceinline__ void mma_bf16(float* d, const uint32_t* a, const uint32_t* b) {
    asm volatile(
        "mma.sync.aligned.m16n8k16.row.col.f32.bf16.bf16.f32 "
        "{%0,%1,%2,%3}, {%4,%5,%6,%7}, {%8,%9}, {%0,%1,%2,%3};"
        : "+f"(d[0]), "+f"(d[1]), "+f"(d[2]), "+f"(d[3])
        : "r"(a[0]), "r"(a[1]), "r"(a[2]), "r"(a[3]), "r"(b[0]), "r"(b[1]));
}
__device__ __forceinline__ uint32_t packbf(float lo, float hi) {
    uint32_t r;
    asm("cvt.rn.bf16x2.f32 %0, %1, %2;" : "=r"(r) : "f"(hi), "f"(lo));
    return r;
}
__device__ __forceinline__ float fast_exp(float x) {
    float t = fmaxf(x * 1.4426950408889634f, -100.f);
    float z = t + 12582912.f;
    int   ni = __float_as_int(z);
    float nf = z - 12582912.f;
    float f  = t - nf;
    float p = 1.33335581e-3f;
    p = fmaf(p, f, 9.61812910e-3f);
    p = fmaf(p, f, 5.55041087e-2f);
    p = fmaf(p, f, 2.40226507e-1f);
    p = fmaf(p, f, 6.93147181e-1f);
    p = fmaf(p, f, 1.0f);
    float sc = __int_as_float((((ni & 0x7FFFFF) - 0x400000) + 127) << 23);
    return p * sc;
}

// window-row (w*64+n) -> flat token index
__device__ __forceinline__ int win_row_to_tok(int row) {
    int w  = row >> 6;
    int n  = row & 63;
    int b  = w >> 8;
    int wy = (w >> 4) & 15;
    int wx = w & 15;
    int iy = n >> 3;
    int ix = n & 7;
    int hr = (wy * WS + iy + SHIFT) & (HW - 1);
    int wr = (wx * WS + ix + SHIFT) & (HW - 1);
    return (b << 14) + (hr << 7) + wr;
}

// ---------------- prep kernels ---------------------------------------------
__global__ void w2bf_kernel(const float* __restrict__ in, __nv_bfloat16* __restrict__ out, int n) {
    int i = blockIdx.x * 256 + threadIdx.x;
    if (i < n) out[i] = __float2bfloat16(in[i]);
}
__global__ void abias_kernel(const float* __restrict__ rpb, float* __restrict__ tab) {
    int i = blockIdx.x * 256 + threadIdx.x;
    if (i >= NH * 64 * 64) return;
    int h = i >> 12;
    int n = (i >> 6) & 63;
    int m = i & 63;
    int iy = n >> 3, ix = n & 7, jy = m >> 3, jx = m & 7;
    int ridx = (iy - jy + 7) * 15 + (ix - jx + 7);
    tab[i] = rpb[ridx * NH + h];
}

// ---------------- LayerNorm1 (gathered) -> bf16 window order ---------------
__global__ __launch_bounds__(256) void ln_kernel(const float* __restrict__ x,
                                                 const float* __restrict__ s,
                                                 const float* __restrict__ b,
                                                 __nv_bfloat16* __restrict__ out) {
    int warp = threadIdx.x >> 5;
    int lane = threadIdx.x & 31;
    int row  = blockIdx.x * 8 + warp;
    int src  = win_row_to_tok(row);
    const float* xp = x + (size_t)src * C;

    float v[6];
    float sum = 0.f, sq = 0.f;
#pragma unroll
    for (int i = 0; i < 6; i++) {
        v[i] = xp[lane + i * 32];
        sum += v[i];
        sq  += v[i] * v[i];
    }
#pragma unroll
    for (int o = 16; o > 0; o >>= 1) {
        sum += __shfl_xor_sync(0xffffffffu, sum, o);
        sq  += __shfl_xor_sync(0xffffffffu, sq, o);
    }
    float mean = sum * (1.f / C);
    float var  = sq * (1.f / C) - mean * mean;
    float rstd = rsqrtf(var + 1e-5f);

    __nv_bfloat16* op = out + (size_t)row * C;
#pragma unroll
    for (int i = 0; i < 6; i++) {
        int c = lane + i * 32;
        op[c] = __float2bfloat16((v[i] - mean) * rstd * s[c] + b[c]);
    }
}

// ---------------- bf16 MMA GEMM for QKV (R3-proven) ------------------------
#define GBM 256
#define GBN 64
#define GBK 32

__global__ __launch_bounds__(256, 2) void qkv_gemm(const __nv_bfloat16* __restrict__ A,
                                                   const __nv_bfloat16* __restrict__ Bm,
                                                   const float* __restrict__ bias,
                                                   __nv_bfloat16* __restrict__ out,
                                                   int M, int N, int K) {
    __shared__ __align__(16) __nv_bfloat16 As[2][GBM * GBK];
    __shared__ __align__(16) __nv_bfloat16 Bs[2][GBK * GBN];

    int tid  = threadIdx.x;
    int wid  = tid >> 5, lane = tid & 31;
    int wm   = (wid & 3) * 64;
    int wn   = (wid >> 2) * 32;
    int m0   = blockIdx.y * GBM;
    int n0   = blockIdx.x * GBN;

    uint32_t sa = smem_u32(&As[0][0]);
    uint32_t sb = smem_u32(&Bs[0][0]);

    uint32_t aoff[4][2], boff[2][2];
#pragma unroll
    for (int ma = 0; ma < 4; ma++)
#pragma unroll
        for (int ks = 0; ks < 2; ks++) {
            int row = wm + ma * 16 + (lane & 7) + 8 * ((lane >> 3) & 1);
            int ch  = 2 * ks + (lane >> 4);
            aoff[ma][ks] = row * 64 + ((ch ^ ((row >> 1) & 3)) << 4);
        }
#pragma unroll
    for (int np = 0; np < 2; np++)
#pragma unroll
        for (int ks = 0; ks < 2; ks++) {
            int k  = ks * 16 + (lane & 7) + 8 * ((lane >> 3) & 1);
            int cn = (wn >> 3) + np * 2 + (lane >> 4);
            boff[np][ks] = k * 128 + ((cn ^ (k & 7)) << 4);
        }

    float acc[4][4][4];
#pragma unroll
    for (int i = 0; i < 4; i++)
#pragma unroll
        for (int j = 0; j < 4; j++)
#pragma unroll
            for (int q = 0; q < 4; q++) acc[i][j][q] = 0.f;

    const int nk = K / GBK;
    int arow = tid >> 2, ac = tid & 3;
    int bk = tid >> 3,  bcn = tid & 7;
    uint32_t adst0 = arow * 64 + ((ac ^ ((arow >> 1) & 3)) << 4);
    uint32_t bdst  = bk * 128 + ((bcn ^ (bk & 7)) << 4);

    auto issue = [&](int kt, int buf) {
        const __nv_bfloat16* ga = A + (size_t)m0 * K + kt * GBK + ac * 8;
#pragma unroll
        for (int p = 0; p < 4; p++) {
            int row = arow + p * 64;
            cpasync16(sa + buf * (GBM * GBK * 2) + adst0 + p * (64 * 64),
                      ga + (size_t)row * K);
        }
        cpasync16(sb + buf * (GBK * GBN * 2) + bdst,
                  Bm + (size_t)(kt * GBK + bk) * N + n0 + bcn * 8);
        asm volatile("cp.async.commit_group;" ::: "memory");
    };

    issue(0, 0);
    int buf = 0;
    for (int kt = 0; kt < nk; kt++) {
        if (kt + 1 < nk) {
            issue(kt + 1, buf ^ 1);
            asm volatile("cp.async.wait_group 1;" ::: "memory");
        } else {
            asm volatile("cp.async.wait_group 0;" ::: "memory");
        }
        __syncthreads();

        uint32_t ab = sa + buf * (GBM * GBK * 2);
        uint32_t bb = sb + buf * (GBK * GBN * 2);
#pragma unroll
        for (int ks = 0; ks < 2; ks++) {
            uint32_t af[4][4], bfr[4][2];
#pragma unroll
            for (int ma = 0; ma < 4; ma++) ldsm_x4(af[ma], ab + aoff[ma][ks]);
#pragma unroll
            for (int np = 0; np < 2; np++) {
                uint32_t t4[4];
                ldsm_x4_t(t4, bb + boff[np][ks]);
                bfr[np * 2][0] = t4[0]; bfr[np * 2][1] = t4[1];
                bfr[np * 2 + 1][0] = t4[2]; bfr[np * 2 + 1][1] = t4[3];
            }
#pragma unroll
            for (int ma = 0; ma < 4; ma++)
#pragma unroll
                for (int nb = 0; nb < 4; nb++)
                    mma_bf16(acc[ma][nb], af[ma], bfr[nb]);
        }
        __syncthreads();
        buf ^= 1;
    }

    int g = lane >> 2, tig = lane & 3;
#pragma unroll
    for (int ma = 0; ma < 4; ma++) {
        int rlo = m0 + wm + ma * 16 + g;
        int rhi = rlo + 8;
#pragma unroll
        for (int nb = 0; nb < 4; nb++) {
            int col = n0 + wn + nb * 8 + tig * 2;
            float bi0 = bias[col], bi1 = bias[col + 1];
            *(uint32_t*)&out[(size_t)rlo * N + col] = packbf(acc[ma][nb][0] + bi0, acc[ma][nb][1] + bi1);
            *(uint32_t*)&out[(size_t)rhi * N + col] = packbf(acc[ma][nb][2] + bi0, acc[ma][nb][3] + bi1);
        }
    }
}

// ---------------- megakernel v2: attention + proj + residual + LN2 ---------
// CTA = 2 windows = 128 rows, 512 threads (16 warps), occ=1.
// smem layout (bytes):
//   sQ [0,49152)       : win*24576 + r*384 + swz(ch, r&7), ch in [0,24)
//   sK [49152,98304)
//   sV [98304,147456)
//   sA [147456,196608) : 128 rows x 384B (attention output, bf16)
//   sW [196608,221184) : Wproj double-buffered 2 x 12288 (32 K-rows x 192)
//   sOut fp32 128x196 overlays [0,100352) after attention.
#define MK_SMEM 221184
#define LNW 196

__global__ __launch_bounds__(512) void attnproj_kernel(const __nv_bfloat16* __restrict__ qkv,
                                                       const float* __restrict__ abias,
                                                       const __nv_bfloat16* __restrict__ wproj,
                                                       const float* __restrict__ pbias,
                                                       const float* __restrict__ x,
                                                       const float* __restrict__ n2s,
                                                       const float* __restrict__ n2b,
                                                       float* __restrict__ x1,
                                                       __nv_bfloat16* __restrict__ xn2) {
    extern __shared__ char sm[];
    uint32_t sq  = smem_u32(sm);
    uint32_t skb = sq + 49152;
    uint32_t svb = sq + 98304;
    uint32_t sab = sq + 147456;
    uint32_t swb = sq + 196608;
    char* sA_p = sm + 147456;
    float* sOut = (float*)sm;

    int tid  = threadIdx.x;
    int wid  = tid >> 5, lane = tid & 31;
    int m0   = blockIdx.x * 128;
    int g = lane >> 2, q2 = (lane & 3) * 2;

    // weight stage loader: stage s = W rows [s*32, s*32+32)
    auto issueW = [&](int s, int buf) {
#pragma unroll
        for (int j = 0; j < 2; j++) {
            int i = tid + j * 512;
            if (i < 768) {
                int kl = i / 24, ch = i % 24;
                cpasync16(swb + buf * 12288 + kl * 384 + ((ch ^ (kl & 7)) << 4),
                          wproj + (size_t)(s * 32 + kl) * 192 + ch * 8);
            }
        }
        asm volatile("cp.async.commit_group;" ::: "memory");
    };

    // one-shot qkv load: 128 rows x 72 chunks = 9216 (group 1)
#pragma unroll
    for (int j = 0; j < 18; j++) {
        int i = tid + j * 512;
        int t = i / 72, cc = i % 72;
        int mat = cc / 24, ch = cc % 24;
        int win = t >> 6, r = t & 63;
        cpasync16(sq + mat * 49152 + win * 24576 + r * 384 + ((ch ^ (r & 7)) << 4),
                  qkv + (size_t)(m0 + t) * 576 + cc * 8);
    }
    asm volatile("cp.async.commit_group;" ::: "memory");
    issueW(0, 0);                                   // group 2, overlaps attention
    asm volatile("cp.async.wait_group 1;" ::: "memory");   // qkv arrived
    __syncthreads();

    // ---------- attention: 48 warp-tasks, 3 per warp, no syncs ----------
#pragma unroll
    for (int it = 0; it < 3; it++) {
        int tk  = wid + it * 16;         // 0..47
        int win = tk / 24;
        int rem = tk - win * 24;
        int hh  = rem >> 2;
        int r4  = rem & 3;
        int r0  = r4 * 16;

        uint32_t qbase = sq  + win * 24576;
        uint32_t kbase = skb + win * 24576;
        uint32_t vbase = svb + win * 24576;

        float sacc[8][4];
#pragma unroll
        for (int i = 0; i < 8; i++)
#pragma unroll
            for (int q = 0; q < 4; q++) sacc[i][q] = 0.f;

        uint32_t qa[2][4];
#pragma unroll
        for (int ks = 0; ks < 2; ks++) {
            int row = r0 + (lane & 7) + 8 * ((lane >> 3) & 1);
            int ch  = hh * 4 + 2 * ks + (lane >> 4);
            ldsm_x4(qa[ks], qbase + row * 384 + ((ch ^ (row & 7)) << 4));
        }
#pragma unroll
        for (int ks = 0; ks < 2; ks++) {
#pragma unroll
            for (int np = 0; np < 4; np++) {
                int tok = np * 16 + (lane & 7) + 8 * (lane >> 4);
                int ch  = hh * 4 + 2 * ks + ((lane >> 3) & 1);
                uint32_t kb[4];
                ldsm_x4(kb, kbase + tok * 384 + ((ch ^ (tok & 7)) << 4));
                mma_bf16(sacc[2 * np],     qa[ks], kb);
                mma_bf16(sacc[2 * np + 1], qa[ks], kb + 2);
            }
        }

        const float scale = 0.17677669529663687f;
        int row0 = r0 + g;
        const float* bt = abias + ((size_t)hh * 64) * 64;
        float mx0 = -1e30f, mx1 = -1e30f;
#pragma unroll
        for (int nb = 0; nb < 8; nb++) {
            int mcol = nb * 8 + q2;
            const float* b0 = bt + row0 * 64 + mcol;
            const float* b1 = b0 + 8 * 64;
            sacc[nb][0] = fmaf(sacc[nb][0], scale, b0[0]);
            sacc[nb][1] = fmaf(sacc[nb][1], scale, b0[1]);
            sacc[nb][2] = fmaf(sacc[nb][2], scale, b1[0]);
            sacc[nb][3] = fmaf(sacc[nb][3], scale, b1[1]);
            mx0 = fmaxf(mx0, fmaxf(sacc[nb][0], sacc[nb][1]));
            mx1 = fmaxf(mx1, fmaxf(sacc[nb][2], sacc[nb][3]));
        }
#pragma unroll
        for (int o = 1; o < 4; o <<= 1) {
            mx0 = fmaxf(mx0, __shfl_xor_sync(0xffffffffu, mx0, o));
            mx1 = fmaxf(mx1, __shfl_xor_sync(0xffffffffu, mx1, o));
        }
        float sum0 = 0.f, sum1 = 0.f;
#pragma unroll
        for (int nb = 0; nb < 8; nb++) {
            sacc[nb][0] = fast_exp(sacc[nb][0] - mx0);
            sacc[nb][1] = fast_exp(sacc[nb][1] - mx0);
            sacc[nb][2] = fast_exp(sacc[nb][2] - mx1);
            sacc[nb][3] = fast_exp(sacc[nb][3] - mx1);
            sum0 += sacc[nb][0] + sacc[nb][1];
            sum1 += sacc[nb][2] + sacc[nb][3];
        }
#pragma unroll
        for (int o = 1; o < 4; o <<= 1) {
            sum0 += __shfl_xor_sync(0xffffffffu, sum0, o);
            sum1 += __shfl_xor_sync(0xffffffffu, sum1, o);
        }

        uint32_t pa[4][4];
#pragma unroll
        for (int ks = 0; ks < 4; ks++) {
            pa[ks][0] = packbf(sacc[2 * ks][0],     sacc[2 * ks][1]);
            pa[ks][1] = packbf(sacc[2 * ks][2],     sacc[2 * ks][3]);
            pa[ks][2] = packbf(sacc[2 * ks + 1][0], sacc[2 * ks + 1][1]);
            pa[ks][3] = packbf(sacc[2 * ks + 1][2], sacc[2 * ks + 1][3]);
        }

        float oacc[4][4];
#pragma unroll
        for (int i = 0; i < 4; i++)
#pragma unroll
            for (int q = 0; q < 4; q++) oacc[i][q] = 0.f;
#pragma unroll
        for (int ks = 0; ks < 4; ks++) {
#pragma unroll
            for (int np = 0; np < 2; np++) {
                int kr = ks * 16 + (lane & 7) + 8 * ((lane >> 3) & 1);
                int cn = hh * 4 + np * 2 + (lane >> 4);
                uint32_t vb[4];
                ldsm_x4_t(vb, vbase + kr * 384 + ((cn ^ (kr & 7)) << 4));
                mma_bf16(oacc[2 * np],     pa[ks], vb);
                mma_bf16(oacc[2 * np + 1], pa[ks], vb + 2);
            }
        }

        float inv0 = 1.f / sum0, inv1 = 1.f / sum1;
        int rl = win * 64 + row0;
        int rh = rl + 8;
#pragma unroll
        for (int nb = 0; nb < 4; nb++) {
            int chA = hh * 4 + nb;
            *(uint32_t*)(sA_p + rl * 384 + ((chA ^ (rl & 7)) << 4) + q2 * 2) =
                packbf(oacc[nb][0] * inv0, oacc[nb][1] * inv0);
            *(uint32_t*)(sA_p + rh * 384 + ((chA ^ (rh & 7)) << 4) + q2 * 2) =
                packbf(oacc[nb][2] * inv1, oacc[nb][3] * inv1);
        }
    }
    __syncthreads();

    // ---------- proj GEMM: [128x192] = sA @ Wproj, 6 streamed stages ------
    int wm = (wid & 3) * 32;
    int wn = (wid >> 2) * 48;
    float acc[2][6][4];
#pragma unroll
    for (int i = 0; i < 2; i++)
#pragma unroll
        for (int j = 0; j < 6; j++)
#pragma unroll
            for (int q = 0; q < 4; q++) acc[i][j][q] = 0.f;

    for (int s = 0; s < 6; s++) {
        if (s < 5) {
            issueW(s + 1, (s + 1) & 1);
            asm volatile("cp.async.wait_group 1;" ::: "memory");
        } else {
            asm volatile("cp.async.wait_group 0;" ::: "memory");
        }
        __syncthreads();
        uint32_t bb = swb + (s & 1) * 12288;
#pragma unroll
        for (int t = 0; t < 2; t++) {
            uint32_t af[2][4];
#pragma unroll
            for (int fi = 0; fi < 2; fi++) {
                int row = wm + fi * 16 + (lane & 7) + 8 * ((lane >> 3) & 1);
                int ch  = 4 * s + 2 * t + (lane >> 4);
                ldsm_x4(af[fi], sab + row * 384 + ((ch ^ (row & 7)) << 4));
            }
            uint32_t bfr[6][2];
#pragma unroll
            for (int j = 0; j < 3; j++) {
                int kl = t * 16 + (lane & 7) + 8 * ((lane >> 3) & 1);
                int cn = (wn >> 3) + 2 * j + (lane >> 4);
                uint32_t t4[4];
                ldsm_x4_t(t4, bb + kl * 384 + ((cn ^ (kl & 7)) << 4));
                bfr[2 * j][0] = t4[0]; bfr[2 * j][1] = t4[1];
                bfr[2 * j + 1][0] = t4[2]; bfr[2 * j + 1][1] = t4[3];
            }
#pragma unroll
            for (int fi = 0; fi < 2; fi++)
#pragma unroll
                for (int nj = 0; nj < 6; nj++)
                    mma_bf16(acc[fi][nj], af[fi], bfr[nj]);
        }
        __syncthreads();
    }

    // epilogue: + bias + gathered residual -> sOut (fp32, overlays sQ/sK)
#pragma unroll
    for (int fi = 0; fi < 2; fi++) {
        int rl = wm + fi * 16 + g;
        int rh = rl + 8;
        int tokl = win_row_to_tok(m0 + rl);
        int tokh = win_row_to_tok(m0 + rh);
#pragma unroll
        for (int nj = 0; nj < 6; nj++) {
            int col = wn + nj * 8 + q2;
            float bi0 = pbias[col], bi1 = pbias[col + 1];
            float2 xl = *(const float2*)&x[(size_t)tokl * C + col];
            float2 xh = *(const float2*)&x[(size_t)tokh * C + col];
            sOut[rl * LNW + col]     = acc[fi][nj][0] + bi0 + xl.x;
            sOut[rl * LNW + col + 1] = acc[fi][nj][1] + bi1 + xl.y;
            sOut[rh * LNW + col]     = acc[fi][nj][2] + bi0 + xh.x;
            sOut[rh * LNW + col + 1] = acc[fi][nj][3] + bi1 + xh.y;
        }
    }
    __syncthreads();

    // LN2: 16 warps x 8 rows, write x1 + xn2 (token order)
    float sg[6], bg[6];
#pragma unroll
    for (int i = 0; i < 6; i++) {
        int c = lane + i * 32;
        sg[i] = n2s[c];
        bg[i] = n2b[c];
    }
#pragma unroll
    for (int rr = 0; rr < 8; rr++) {
        int row = wid * 8 + rr;
        const float* rp = sOut + row * LNW;
        float v[6];
        float sum = 0.f, sq2 = 0.f;
#pragma unroll
        for (int i = 0; i < 6; i++) {
            v[i] = rp[lane + i * 32];
            sum += v[i];
            sq2 += v[i] * v[i];
        }
#pragma unroll
        for (int o = 16; o > 0; o >>= 1) {
            sum += __shfl_xor_sync(0xffffffffu, sum, o);
            sq2 += __shfl_xor_sync(0xffffffffu, sq2, o);
        }
        float mean = sum * (1.f / C);
        float var  = sq2 * (1.f / C) - mean * mean;
        float rstd = rsqrtf(var + 1e-5f);

        int tok = win_row_to_tok(m0 + row);
        float* x1p = x1 + (size_t)tok * C;
        __nv_bfloat16* xnp = xn2 + (size_t)tok * C;
#pragma unroll
        for (int i = 0; i < 6; i++) {
            int c = lane + i * 32;
            x1p[c] = v[i];
            xnp[c] = __float2bfloat16((v[i] - mean) * rstd * sg[i] + bg[i]);
        }
    }
}

// ---------------- fused MLP (R6-proven): out = gelu(xn2@W1+b1)@W2+b2+x1 ----
#define MLP_SMEM 73728

__device__ __forceinline__ void mlp_gemm_inner(uint32_t aBase, uint32_t sbBase,
                                               const __nv_bfloat16* __restrict__ Wg,
                                               int rstride, int rowbase, int coloff,
                                               int wm, int wn, int tid, int lane,
                                               float acc[2][6][4]) {
    auto issueW = [&](int s, int buf) {
#pragma unroll
        for (int j = 0; j < 3; j++) {
            int i = tid + j * 256;
            int kl = i / 24, cch = i % 24;
            cpasync16(sbBase + buf * 12288 + kl * 384 + ((cch ^ (kl & 7)) << 4),
                      Wg + (size_t)(rowbase + s * 32 + kl) * rstride + coloff + cch * 8);
        }
        asm volatile("cp.async.commit_group;" ::: "memory");
    };

    issueW(0, 0);
    for (int s = 0; s < 6; s++) {
        if (s < 5) {
            issueW(s + 1, (s + 1) & 1);
            asm volatile("cp.async.wait_group 1;" ::: "memory");
        } else {
            asm volatile("cp.async.wait_group 0;" ::: "memory");
        }
        __syncthreads();
        uint32_t bb = sbBase + (s & 1) * 12288;
#pragma unroll
        for (int t = 0; t < 2; t++) {
            int kk = s * 2 + t;
            uint32_t af[2][4];
#pragma unroll
            for (int fi = 0; fi < 2; fi++) {
                int row = wm + fi * 16 + (lane & 7) + 8 * ((lane >> 3) & 1);
                int ch  = 2 * kk + (lane >> 4);
                ldsm_x4(af[fi], aBase + row * 384 + ((ch ^ (row & 7)) << 4));
            }
            uint32_t bfr[6][2];
#pragma unroll
            for (int j = 0; j < 3; j++) {
                int kl = t * 16 + (lane & 7) + 8 * ((lane >> 3) & 1);
                int cn = (wn >> 3) + 2 * j + (lane >> 4);
                uint32_t t4[4];
                ldsm_x4_t(t4, bb + kl * 384 + ((cn ^ (kl & 7)) << 4));
                bfr[2 * j][0] = t4[0]; bfr[2 * j][1] = t4[1];
                bfr[2 * j + 1][0] = t4[2]; bfr[2 * j + 1][1] = t4[3];
            }
#pragma unroll
            for (int fi = 0; fi < 2; fi++)
#pragma unroll
                for (int nj = 0; nj < 6; nj++)
                    mma_bf16(acc[fi][nj], af[fi], bfr[nj]);
        }
        __syncthreads();
    }
}

__global__ __launch_bounds__(256) void mlp_kernel(const __nv_bfloat16* __restrict__ xn,
                                                  const __nv_bfloat16* __restrict__ w1,
                                                  const float* __restrict__ b1,
                                                  const __nv_bfloat16* __restrict__ w2,
                                                  const float* __restrict__ b2,
                                                  const float* __restrict__ x1,
                                                  float* __restrict__ out) {
    extern __shared__ char sm[];
    char* sH_p = sm + 24576;
    uint32_t sxn = smem_u32(sm);
    uint32_t shb = sxn + 24576;
    uint32_t sbb = sxn + 49152;

    int tid = threadIdx.x;
    int wid = tid >> 5, lane = tid & 31;
    int m0 = blockIdx.x * 64;
    int wm = (wid & 1) * 32;
    int wn = (wid >> 1) * 48;
    int g = lane >> 2, q2 = (lane & 3) * 2;

#pragma unroll
    for (int j = 0; j < 6; j++) {
        int i = tid + j * 256;
        int r = i / 24, cch = i % 24;
        cpasync16(sxn + r * 384 + ((cch ^ (r & 7)) << 4), xn + (size_t)(m0 + r) * C + cch * 8);
    }
    asm volatile("cp.async.commit_group;" ::: "memory");
    asm volatile("cp.async.wait_group 0;" ::: "memory");
    __syncthreads();

    float acc2[2][6][4];
#pragma unroll
    for (int i = 0; i < 2; i++)
#pragma unroll
        for (int j = 0; j < 6; j++)
#pragma unroll
            for (int q = 0; q < 4; q++) acc2[i][j][q] = 0.f;

    for (int c = 0; c < 4; c++) {
        float acc1[2][6][4];
#pragma unroll
        for (int i = 0; i < 2; i++)
#pragma unroll
            for (int j = 0; j < 6; j++)
#pragma unroll
                for (int q = 0; q < 4; q++) acc1[i][j][q] = 0.f;
        mlp_gemm_inner(sxn, sbb, w1, 4 * C, 0, c * 192, wm, wn, tid, lane, acc1);

        const float is2 = 0.70710678118654752f;
#pragma unroll
        for (int fi = 0; fi < 2; fi++) {
            int rl = wm + fi * 16 + g;
            int rh = rl + 8;
#pragma unroll
            for (int nj = 0; nj < 6; nj++) {
                int colL = wn + nj * 8 + q2;
                int gcol = c * 192 + colL;
                float bi0 = b1[gcol], bi1 = b1[gcol + 1];
                float v00 = acc1[fi][nj][0] + bi0;
                float v01 = acc1[fi][nj][1] + bi1;
                float v10 = acc1[fi][nj][2] + bi0;
                float v11 = acc1[fi][nj][3] + bi1;
                v00 = 0.5f * v00 * (1.f + erff(v00 * is2));
                v01 = 0.5f * v01 * (1.f + erff(v01 * is2));
                v10 = 0.5f * v10 * (1.f + erff(v10 * is2));
                v11 = 0.5f * v11 * (1.f + erff(v11 * is2));
                int chh = colL >> 3;
                *(uint32_t*)(sH_p + rl * 384 + ((chh ^ (rl & 7)) << 4) + q2 * 2) = packbf(v00, v01);
                *(uint32_t*)(sH_p + rh * 384 + ((chh ^ (rh & 7)) << 4) + q2 * 2) = packbf(v10, v11);
            }
        }
        __syncthreads();

        mlp_gemm_inner(shb, sbb, w2, C, c * 192, 0, wm, wn, tid, lane, acc2);
    }

#pragma unroll
    for (int fi = 0; fi < 2; fi++) {
        int ml = m0 + wm + fi * 16 + g;
        int mh = ml + 8;
#pragma unroll
        for (int nj = 0; nj < 6; nj++) {
            int col = wn + nj * 8 + q2;
            float bi0 = b2[col], bi1 = b2[col + 1];
            float2 xl = *(const float2*)&x1[(size_t)ml * C + col];
            float2 xh = *(const float2*)&x1[(size_t)mh * C + col];
            *(float2*)&out[(size_t)ml * C + col] =
                make_float2(acc2[fi][nj][0] + bi0 + xl.x, acc2[fi][nj][1] + bi1 + xl.y);
            *(float2*)&out[(size_t)mh * C + col] =
                make_float2(acc2[fi][nj][2] + bi0 + xh.x, acc2[fi][nj][3] + bi1 + xh.y);
        }
    }
}

// ---------------- launch ---------------------------------------------------
extern "C" void kernel_launch(void* const* d_in, const int* in_sizes, int n_in,
                              void* d_out, int out_size) {
    const float* x      = (const float*)d_in[0];
    const float* qkv_w  = (const float*)d_in[1];
    const float* qkv_b  = (const float*)d_in[2];
    const float* proj_w = (const float*)d_in[3];
    const float* proj_b = (const float*)d_in[4];
    const float* rpb    = (const float*)d_in[5];
    const float* n1s    = (const float*)d_in[6];
    const float* n1b    = (const float*)d_in[7];
    const float* n2s    = (const float*)d_in[8];
    const float* n2b    = (const float*)d_in[9];
    const float* w1     = (const float*)d_in[10];
    const float* b1     = (const float*)d_in[11];
    const float* w2     = (const float*)d_in[12];
    const float* b2     = (const float*)d_in[13];
    float* out = (float*)d_out;

    __nv_bfloat16 *xw, *qkv, *xn2, *wqkv, *wproj, *ww1, *ww2;
    float *x1, *abias;
    cudaGetSymbolAddress((void**)&xw,    g_xw);
    cudaGetSymbolAddress((void**)&qkv,   g_qkv);
    cudaGetSymbolAddress((void**)&x1,    g_x1);
    cudaGetSymbolAddress((void**)&xn2,   g_xn2);
    cudaGetSymbolAddress((void**)&wqkv,  g_wqkv);
    cudaGetSymbolAddress((void**)&wproj, g_wproj);
    cudaGetSymbolAddress((void**)&ww1,   g_w1);
    cudaGetSymbolAddress((void**)&ww2,   g_w2);
    cudaGetSymbolAddress((void**)&abias, g_abias);

    cudaFuncSetAttribute(attnproj_kernel, cudaFuncAttributeMaxDynamicSharedMemorySize, MK_SMEM);
    cudaFuncSetAttribute(mlp_kernel,      cudaFuncAttributeMaxDynamicSharedMemorySize, MLP_SMEM);

    // prep
    w2bf_kernel<<<(C * 3 * C + 255) / 256, 256>>>(qkv_w,  wqkv,  C * 3 * C);
    w2bf_kernel<<<(C * C + 255) / 256,     256>>>(proj_w, wproj, C * C);
    w2bf_kernel<<<(C * 4 * C + 255) / 256, 256>>>(w1,     ww1,   C * 4 * C);
    w2bf_kernel<<<(4 * C * C + 255) / 256, 256>>>(w2,     ww2,   4 * C * C);
    abias_kernel<<<(NH * 64 * 64 + 255) / 256, 256>>>(rpb, abias);

    // 1. LN1 + shift + window gather -> bf16
    ln_kernel<<<NTOK / 8, 256>>>(x, n1s, n1b, xw);

    // 2. QKV GEMM -> bf16
    qkv_gemm<<<dim3((3 * C) / GBN, NTOK / GBM), 256>>>(xw, wqkv, qkv_b, qkv,
                                                       NTOK, 3 * C, C);

    // 3. attention + proj + residual + LN2 -> x1 (fp32) & xn2 (bf16)
    attnproj_kernel<<<NTOK / 128, 512, MK_SMEM>>>(qkv, abias, wproj, proj_b,
                                                  x, n2s, n2b, x1, xn2);

    // 4. fused MLP + residual -> out
    mlp_kernel<<<NTOK / 64, 256, MLP_SMEM>>>(xn2, ww1, b1, ww2, b2, x1, out);
}

// round 8
// speedup vs baseline: 5.7999x; 1.0404x over previous
#include <cuda_runtime.h>
#include <cuda_bf16.h>
#include <math.h>
#include <stdint.h>

// Problem constants
#define BATCH   8
#define HW      128
#define LTOK    16384
#define C       192
#define WS      8
#define SHIFT   4
#define NH      6
#define HD      32
#define NWIN    2048
#define NTOK    131072

// ---------------- scratch (device globals) ---------------------------------
__device__ __nv_bfloat16 g_xw  [(size_t)NTOK * C];
__device__ __nv_bfloat16 g_qkv [(size_t)NTOK * 3 * C];
__device__ float         g_x1  [(size_t)NTOK * C];
__device__ __nv_bfloat16 g_xn2 [(size_t)NTOK * C];
__device__ __nv_bfloat16 g_wqkv [C * 3 * C];    // [K,N] bf16
__device__ __nv_bfloat16 g_wproj[C * C];        // [K,N] bf16
__device__ __nv_bfloat16 g_w1   [C * 4 * C];    // [K,N] bf16
__device__ __nv_bfloat16 g_w2   [4 * C * C];    // [K,N] bf16
__device__ float         g_abias[NH * 64 * 64];

// ---------------- helpers --------------------------------------------------
__device__ __forceinline__ uint32_t smem_u32(const void* p) {
    return (uint32_t)__cvta_generic_to_shared(p);
}
__device__ __forceinline__ void cpasync16(uint32_t dst, const void* src) {
    asm volatile("cp.async.cg.shared.global [%0], [%1], 16;" :: "r"(dst), "l"(src));
}
__device__ __forceinline__ void ldsm_x4(uint32_t* r, uint32_t addr) {
    asm volatile("ldmatrix.sync.aligned.m8n8.x4.shared.b16 {%0,%1,%2,%3}, [%4];"
        : "=r"(r[0]), "=r"(r[1]), "=r"(r[2]), "=r"(r[3]) : "r"(addr));
}
__device__ __forceinline__ void ldsm_x4_t(uint32_t* r, uint32_t addr) {
    asm volatile("ldmatrix.sync.aligned.m8n8.x4.trans.shared.b16 {%0,%1,%2,%3}, [%4];"
        : "=r"(r[0]), "=r"(r[1]), "=r"(r[2]), "=r"(r[3]) : "r"(addr));
}
__device__ __forceinline__ void mma_bf16(float* d, const uint32_t* a, const uint32_t* b) {
    asm volatile(
        "mma.sync.aligned.m16n8k16.row.col.f32.bf16.bf16.f32 "
        "{%0,%1,%2,%3}, {%4,%5,%6,%7}, {%8,%9}, {%0,%1,%2,%3};"
        : "+f"(d[0]), "+f"(d[1]), "+f"(d[2]), "+f"(d[3])
        : "r"(a[0]), "r"(a[1]), "r"(a[2]), "r"(a[3]), "r"(b[0]), "r"(b[1]));
}
__device__ __forceinline__ uint32_t packbf(float lo, float hi) {
    uint32_t r;
    asm("cvt.rn.bf16x2.f32 %0, %1, %2;" : "=r"(r) : "f"(hi), "f"(lo));
    return r;
}
__device__ __forceinline__ float fast_exp(float x) {
    float t = fmaxf(x * 1.4426950408889634f, -100.f);
    float z = t + 12582912.f;
    int   ni = __float_as_int(z);
    float nf = z - 12582912.f;
    float f  = t - nf;
    float p = 1.33335581e-3f;
    p = fmaf(p, f, 9.61812910e-3f);
    p = fmaf(p, f, 5.55041087e-2f);
    p = fmaf(p, f, 2.40226507e-1f);
    p = fmaf(p, f, 6.93147181e-1f);
    p = fmaf(p, f, 1.0f);
    float sc = __int_as_float((((ni & 0x7FFFFF) - 0x400000) + 127) << 23);
    return p * sc;
}

// window-row (w*64+n) -> flat token index
__device__ __forceinline__ int win_row_to_tok(int row) {
    int w  = row >> 6;
    int n  = row & 63;
    int b  = w >> 8;
    int wy = (w >> 4) & 15;
    int wx = w & 15;
    int iy = n >> 3;
    int ix = n & 7;
    int hr = (wy * WS + iy + SHIFT) & (HW - 1);
    int wr = (wx * WS + ix + SHIFT) & (HW - 1);
    return (b << 14) + (hr << 7) + wr;
}

// ---------------- merged prep kernel ---------------------------------------
// region sizes (elements)
#define SZ_QKVW (C * 3 * C)       // 110592
#define SZ_PROJ (C * C)           // 36864
#define SZ_W1   (C * 4 * C)       // 147456
#define SZ_W2   (4 * C * C)       // 147456
#define SZ_ALL  (SZ_QKVW + SZ_PROJ + SZ_W1 + SZ_W2)   // 442368

__global__ __launch_bounds__(256) void prep_w_kernel(const float* __restrict__ qkv_w,
                                                     const float* __restrict__ proj_w,
                                                     const float* __restrict__ w1,
                                                     const float* __restrict__ w2,
                                                     __nv_bfloat16* __restrict__ wqkv,
                                                     __nv_bfloat16* __restrict__ wproj,
                                                     __nv_bfloat16* __restrict__ ow1,
                                                     __nv_bfloat16* __restrict__ ow2) {
    int i = blockIdx.x * 256 + threadIdx.x;
    if (i >= SZ_ALL) return;
    if (i < SZ_QKVW) {
        wqkv[i] = __float2bfloat16(qkv_w[i]);
    } else if (i < SZ_QKVW + SZ_PROJ) {
        int j = i - SZ_QKVW;
        wproj[j] = __float2bfloat16(proj_w[j]);
    } else if (i < SZ_QKVW + SZ_PROJ + SZ_W1) {
        int j = i - SZ_QKVW - SZ_PROJ;
        ow1[j] = __float2bfloat16(w1[j]);
    } else {
        int j = i - SZ_QKVW - SZ_PROJ - SZ_W1;
        ow2[j] = __float2bfloat16(w2[j]);
    }
}
__global__ void abias_kernel(const float* __restrict__ rpb, float* __restrict__ tab) {
    int i = blockIdx.x * 256 + threadIdx.x;
    if (i >= NH * 64 * 64) return;
    int h = i >> 12;
    int n = (i >> 6) & 63;
    int m = i & 63;
    int iy = n >> 3, ix = n & 7, jy = m >> 3, jx = m & 7;
    int ridx = (iy - jy + 7) * 15 + (ix - jx + 7);
    tab[i] = rpb[ridx * NH + h];
}

// ---------------- LayerNorm1 (gathered) -> bf16, vectorized ----------------
__global__ __launch_bounds__(256) void ln_kernel(const float* __restrict__ x,
                                                 const float* __restrict__ s,
                                                 const float* __restrict__ b,
                                                 __nv_bfloat16* __restrict__ out) {
    int warp = threadIdx.x >> 5;
    int lane = threadIdx.x & 31;
    int row  = blockIdx.x * 8 + warp;
    int src  = win_row_to_tok(row);
    const float2* xp = (const float2*)(x + (size_t)src * C);
    const float2* sp = (const float2*)s;
    const float2* bp = (const float2*)b;

    float2 v[3];
    float sum = 0.f, sq = 0.f;
#pragma unroll
    for (int i = 0; i < 3; i++) {
        v[i] = xp[lane + i * 32];
        sum += v[i].x + v[i].y;
        sq  += v[i].x * v[i].x + v[i].y * v[i].y;
    }
#pragma unroll
    for (int o = 16; o > 0; o >>= 1) {
        sum += __shfl_xor_sync(0xffffffffu, sum, o);
        sq  += __shfl_xor_sync(0xffffffffu, sq, o);
    }
    float mean = sum * (1.f / C);
    float var  = sq * (1.f / C) - mean * mean;
    float rstd = rsqrtf(var + 1e-5f);

    uint32_t* op = (uint32_t*)(out + (size_t)row * C);
#pragma unroll
    for (int i = 0; i < 3; i++) {
        int c2 = lane + i * 32;
        float2 sv = sp[c2], bv = bp[c2];
        op[c2] = packbf((v[i].x - mean) * rstd * sv.x + bv.x,
                        (v[i].y - mean) * rstd * sv.y + bv.y);
    }
}

// ---------------- bf16 MMA GEMM for QKV (R3-proven) ------------------------
#define GBM 256
#define GBN 64
#define GBK 32

__global__ __launch_bounds__(256, 2) void qkv_gemm(const __nv_bfloat16* __restrict__ A,
                                                   const __nv_bfloat16* __restrict__ Bm,
                                                   const float* __restrict__ bias,
                                                   __nv_bfloat16* __restrict__ out,
                                                   int M, int N, int K) {
    __shared__ __align__(16) __nv_bfloat16 As[2][GBM * GBK];
    __shared__ __align__(16) __nv_bfloat16 Bs[2][GBK * GBN];

    int tid  = threadIdx.x;
    int wid  = tid >> 5, lane = tid & 31;
    int wm   = (wid & 3) * 64;
    int wn   = (wid >> 2) * 32;
    int m0   = blockIdx.y * GBM;
    int n0   = blockIdx.x * GBN;

    uint32_t sa = smem_u32(&As[0][0]);
    uint32_t sb = smem_u32(&Bs[0][0]);

    uint32_t aoff[4][2], boff[2][2];
#pragma unroll
    for (int ma = 0; ma < 4; ma++)
#pragma unroll
        for (int ks = 0; ks < 2; ks++) {
            int row = wm + ma * 16 + (lane & 7) + 8 * ((lane >> 3) & 1);
            int ch  = 2 * ks + (lane >> 4);
            aoff[ma][ks] = row * 64 + ((ch ^ ((row >> 1) & 3)) << 4);
        }
#pragma unroll
    for (int np = 0; np < 2; np++)
#pragma unroll
        for (int ks = 0; ks < 2; ks++) {
            int k  = ks * 16 + (lane & 7) + 8 * ((lane >> 3) & 1);
            int cn = (wn >> 3) + np * 2 + (lane >> 4);
            boff[np][ks] = k * 128 + ((cn ^ (k & 7)) << 4);
        }

    float acc[4][4][4];
#pragma unroll
    for (int i = 0; i < 4; i++)
#pragma unroll
        for (int j = 0; j < 4; j++)
#pragma unroll
            for (int q = 0; q < 4; q++) acc[i][j][q] = 0.f;

    const int nk = K / GBK;
    int arow = tid >> 2, ac = tid & 3;
    int bk = tid >> 3,  bcn = tid & 7;
    uint32_t adst0 = arow * 64 + ((ac ^ ((arow >> 1) & 3)) << 4);
    uint32_t bdst  = bk * 128 + ((bcn ^ (bk & 7)) << 4);

    auto issue = [&](int kt, int buf) {
        const __nv_bfloat16* ga = A + (size_t)m0 * K + kt * GBK + ac * 8;
#pragma unroll
        for (int p = 0; p < 4; p++) {
            int row = arow + p * 64;
            cpasync16(sa + buf * (GBM * GBK * 2) + adst0 + p * (64 * 64),
                      ga + (size_t)row * K);
        }
        cpasync16(sb + buf * (GBK * GBN * 2) + bdst,
                  Bm + (size_t)(kt * GBK + bk) * N + n0 + bcn * 8);
        asm volatile("cp.async.commit_group;" ::: "memory");
    };

    issue(0, 0);
    int buf = 0;
    for (int kt = 0; kt < nk; kt++) {
        if (kt + 1 < nk) {
            issue(kt + 1, buf ^ 1);
            asm volatile("cp.async.wait_group 1;" ::: "memory");
        } else {
            asm volatile("cp.async.wait_group 0;" ::: "memory");
        }
        __syncthreads();

        uint32_t ab = sa + buf * (GBM * GBK * 2);
        uint32_t bb = sb + buf * (GBK * GBN * 2);
#pragma unroll
        for (int ks = 0; ks < 2; ks++) {
            uint32_t af[4][4], bfr[4][2];
#pragma unroll
            for (int ma = 0; ma < 4; ma++) ldsm_x4(af[ma], ab + aoff[ma][ks]);
#pragma unroll
            for (int np = 0; np < 2; np++) {
                uint32_t t4[4];
                ldsm_x4_t(t4, bb + boff[np][ks]);
                bfr[np * 2][0] = t4[0]; bfr[np * 2][1] = t4[1];
                bfr[np * 2 + 1][0] = t4[2]; bfr[np * 2 + 1][1] = t4[3];
            }
#pragma unroll
            for (int ma = 0; ma < 4; ma++)
#pragma unroll
                for (int nb = 0; nb < 4; nb++)
                    mma_bf16(acc[ma][nb], af[ma], bfr[nb]);
        }
        __syncthreads();
        buf ^= 1;
    }

    int g = lane >> 2, tig = lane & 3;
#pragma unroll
    for (int ma = 0; ma < 4; ma++) {
        int rlo = m0 + wm + ma * 16 + g;
        int rhi = rlo + 8;
#pragma unroll
        for (int nb = 0; nb < 4; nb++) {
            int col = n0 + wn + nb * 8 + tig * 2;
            float bi0 = bias[col], bi1 = bias[col + 1];
            *(uint32_t*)&out[(size_t)rlo * N + col] = packbf(acc[ma][nb][0] + bi0, acc[ma][nb][1] + bi1);
            *(uint32_t*)&out[(size_t)rhi * N + col] = packbf(acc[ma][nb][2] + bi0, acc[ma][nb][3] + bi1);
        }
    }
}

// ---------------- megakernel: attention + proj + residual + LN2 (R7) -------
#define MK_SMEM 221184
#define LNW 196

__global__ __launch_bounds__(512) void attnproj_kernel(const __nv_bfloat16* __restrict__ qkv,
                                                       const float* __restrict__ abias,
                                                       const __nv_bfloat16* __restrict__ wproj,
                                                       const float* __restrict__ pbias,
                                                       const float* __restrict__ x,
                                                       const float* __restrict__ n2s,
                                                       const float* __restrict__ n2b,
                                                       float* __restrict__ x1,
                                                       __nv_bfloat16* __restrict__ xn2) {
    extern __shared__ char sm[];
    uint32_t sq  = smem_u32(sm);
    uint32_t skb = sq + 49152;
    uint32_t svb = sq + 98304;
    uint32_t sab = sq + 147456;
    uint32_t swb = sq + 196608;
    char* sA_p = sm + 147456;
    float* sOut = (float*)sm;

    int tid  = threadIdx.x;
    int wid  = tid >> 5, lane = tid & 31;
    int m0   = blockIdx.x * 128;
    int g = lane >> 2, q2 = (lane & 3) * 2;

    auto issueW = [&](int s, int buf) {
#pragma unroll
        for (int j = 0; j < 2; j++) {
            int i = tid + j * 512;
            if (i < 768) {
                int kl = i / 24, ch = i % 24;
                cpasync16(swb + buf * 12288 + kl * 384 + ((ch ^ (kl & 7)) << 4),
                          wproj + (size_t)(s * 32 + kl) * 192 + ch * 8);
            }
        }
        asm volatile("cp.async.commit_group;" ::: "memory");
    };

#pragma unroll
    for (int j = 0; j < 18; j++) {
        int i = tid + j * 512;
        int t = i / 72, cc = i % 72;
        int mat = cc / 24, ch = cc % 24;
        int win = t >> 6, r = t & 63;
        cpasync16(sq + mat * 49152 + win * 24576 + r * 384 + ((ch ^ (r & 7)) << 4),
                  qkv + (size_t)(m0 + t) * 576 + cc * 8);
    }
    asm volatile("cp.async.commit_group;" ::: "memory");
    issueW(0, 0);
    asm volatile("cp.async.wait_group 1;" ::: "memory");
    __syncthreads();

#pragma unroll
    for (int it = 0; it < 3; it++) {
        int tk  = wid + it * 16;
        int win = tk / 24;
        int rem = tk - win * 24;
        int hh  = rem >> 2;
        int r4  = rem & 3;
        int r0  = r4 * 16;

        uint32_t qbase = sq  + win * 24576;
        uint32_t kbase = skb + win * 24576;
        uint32_t vbase = svb + win * 24576;

        float sacc[8][4];
#pragma unroll
        for (int i = 0; i < 8; i++)
#pragma unroll
            for (int q = 0; q < 4; q++) sacc[i][q] = 0.f;

        uint32_t qa[2][4];
#pragma unroll
        for (int ks = 0; ks < 2; ks++) {
            int row = r0 + (lane & 7) + 8 * ((lane >> 3) & 1);
            int ch  = hh * 4 + 2 * ks + (lane >> 4);
            ldsm_x4(qa[ks], qbase + row * 384 + ((ch ^ (row & 7)) << 4));
        }
#pragma unroll
        for (int ks = 0; ks < 2; ks++) {
#pragma unroll
            for (int np = 0; np < 4; np++) {
                int tok = np * 16 + (lane & 7) + 8 * (lane >> 4);
                int ch  = hh * 4 + 2 * ks + ((lane >> 3) & 1);
                uint32_t kb[4];
                ldsm_x4(kb, kbase + tok * 384 + ((ch ^ (tok & 7)) << 4));
                mma_bf16(sacc[2 * np],     qa[ks], kb);
                mma_bf16(sacc[2 * np + 1], qa[ks], kb + 2);
            }
        }

        const float scale = 0.17677669529663687f;
        int row0 = r0 + g;
        const float* bt = abias + ((size_t)hh * 64) * 64;
        float mx0 = -1e30f, mx1 = -1e30f;
#pragma unroll
        for (int nb = 0; nb < 8; nb++) {
            int mcol = nb * 8 + q2;
            const float* b0 = bt + row0 * 64 + mcol;
            const float* b1 = b0 + 8 * 64;
            sacc[nb][0] = fmaf(sacc[nb][0], scale, b0[0]);
            sacc[nb][1] = fmaf(sacc[nb][1], scale, b0[1]);
            sacc[nb][2] = fmaf(sacc[nb][2], scale, b1[0]);
            sacc[nb][3] = fmaf(sacc[nb][3], scale, b1[1]);
            mx0 = fmaxf(mx0, fmaxf(sacc[nb][0], sacc[nb][1]));
            mx1 = fmaxf(mx1, fmaxf(sacc[nb][2], sacc[nb][3]));
        }
#pragma unroll
        for (int o = 1; o < 4; o <<= 1) {
            mx0 = fmaxf(mx0, __shfl_xor_sync(0xffffffffu, mx0, o));
            mx1 = fmaxf(mx1, __shfl_xor_sync(0xffffffffu, mx1, o));
        }
        float sum0 = 0.f, sum1 = 0.f;
#pragma unroll
        for (int nb = 0; nb < 8; nb++) {
            sacc[nb][0] = fast_exp(sacc[nb][0] - mx0);
            sacc[nb][1] = fast_exp(sacc[nb][1] - mx0);
            sacc[nb][2] = fast_exp(sacc[nb][2] - mx1);
            sacc[nb][3] = fast_exp(sacc[nb][3] - mx1);
            sum0 += sacc[nb][0] + sacc[nb][1];
            sum1 += sacc[nb][2] + sacc[nb][3];
        }
#pragma unroll
        for (int o = 1; o < 4; o <<= 1) {
            sum0 += __shfl_xor_sync(0xffffffffu, sum0, o);
            sum1 += __shfl_xor_sync(0xffffffffu, sum1, o);
        }

        uint32_t pa[4][4];
#pragma unroll
        for (int ks = 0; ks < 4; ks++) {
            pa[ks][0] = packbf(sacc[2 * ks][0],     sacc[2 * ks][1]);
            pa[ks][1] = packbf(sacc[2 * ks][2],     sacc[2 * ks][3]);
            pa[ks][2] = packbf(sacc[2 * ks + 1][0], sacc[2 * ks + 1][1]);
            pa[ks][3] = packbf(sacc[2 * ks + 1][2], sacc[2 * ks + 1][3]);
        }

        float oacc[4][4];
#pragma unroll
        for (int i = 0; i < 4; i++)
#pragma unroll
            for (int q = 0; q < 4; q++) oacc[i][q] = 0.f;
#pragma unroll
        for (int ks = 0; ks < 4; ks++) {
#pragma unroll
            for (int np = 0; np < 2; np++) {
                int kr = ks * 16 + (lane & 7) + 8 * ((lane >> 3) & 1);
                int cn = hh * 4 + np * 2 + (lane >> 4);
                uint32_t vb[4];
                ldsm_x4_t(vb, vbase + kr * 384 + ((cn ^ (kr & 7)) << 4));
                mma_bf16(oacc[2 * np],     pa[ks], vb);
                mma_bf16(oacc[2 * np + 1], pa[ks], vb + 2);
            }
        }

        float inv0 = 1.f / sum0, inv1 = 1.f / sum1;
        int rl = win * 64 + row0;
        int rh = rl + 8;
#pragma unroll
        for (int nb = 0; nb < 4; nb++) {
            int chA = hh * 4 + nb;
            *(uint32_t*)(sA_p + rl * 384 + ((chA ^ (rl & 7)) << 4) + q2 * 2) =
                packbf(oacc[nb][0] * inv0, oacc[nb][1] * inv0);
            *(uint32_t*)(sA_p + rh * 384 + ((chA ^ (rh & 7)) << 4) + q2 * 2) =
                packbf(oacc[nb][2] * inv1, oacc[nb][3] * inv1);
        }
    }
    __syncthreads();

    int wm = (wid & 3) * 32;
    int wn = (wid >> 2) * 48;
    float acc[2][6][4];
#pragma unroll
    for (int i = 0; i < 2; i++)
#pragma unroll
        for (int j = 0; j < 6; j++)
#pragma unroll
            for (int q = 0; q < 4; q++) acc[i][j][q] = 0.f;

    for (int s = 0; s < 6; s++) {
        if (s < 5) {
            issueW(s + 1, (s + 1) & 1);
            asm volatile("cp.async.wait_group 1;" ::: "memory");
        } else {
            asm volatile("cp.async.wait_group 0;" ::: "memory");
        }
        __syncthreads();
        uint32_t bb = swb + (s & 1) * 12288;
#pragma unroll
        for (int t = 0; t < 2; t++) {
            uint32_t af[2][4];
#pragma unroll
            for (int fi = 0; fi < 2; fi++) {
                int row = wm + fi * 16 + (lane & 7) + 8 * ((lane >> 3) & 1);
                int ch  = 4 * s + 2 * t + (lane >> 4);
                ldsm_x4(af[fi], sab + row * 384 + ((ch ^ (row & 7)) << 4));
            }
            uint32_t bfr[6][2];
#pragma unroll
            for (int j = 0; j < 3; j++) {
                int kl = t * 16 + (lane & 7) + 8 * ((lane >> 3) & 1);
                int cn = (wn >> 3) + 2 * j + (lane >> 4);
                uint32_t t4[4];
                ldsm_x4_t(t4, bb + kl * 384 + ((cn ^ (kl & 7)) << 4));
                bfr[2 * j][0] = t4[0]; bfr[2 * j][1] = t4[1];
                bfr[2 * j + 1][0] = t4[2]; bfr[2 * j + 1][1] = t4[3];
            }
#pragma unroll
            for (int fi = 0; fi < 2; fi++)
#pragma unroll
                for (int nj = 0; nj < 6; nj++)
                    mma_bf16(acc[fi][nj], af[fi], bfr[nj]);
        }
        __syncthreads();
    }

#pragma unroll
    for (int fi = 0; fi < 2; fi++) {
        int rl = wm + fi * 16 + g;
        int rh = rl + 8;
        int tokl = win_row_to_tok(m0 + rl);
        int tokh = win_row_to_tok(m0 + rh);
#pragma unroll
        for (int nj = 0; nj < 6; nj++) {
            int col = wn + nj * 8 + q2;
            float bi0 = pbias[col], bi1 = pbias[col + 1];
            float2 xl = *(const float2*)&x[(size_t)tokl * C + col];
            float2 xh = *(const float2*)&x[(size_t)tokh * C + col];
            sOut[rl * LNW + col]     = acc[fi][nj][0] + bi0 + xl.x;
            sOut[rl * LNW + col + 1] = acc[fi][nj][1] + bi1 + xl.y;
            sOut[rh * LNW + col]     = acc[fi][nj][2] + bi0 + xh.x;
            sOut[rh * LNW + col + 1] = acc[fi][nj][3] + bi1 + xh.y;
        }
    }
    __syncthreads();

    float sg[6], bg[6];
#pragma unroll
    for (int i = 0; i < 6; i++) {
        int c = lane + i * 32;
        sg[i] = n2s[c];
        bg[i] = n2b[c];
    }
#pragma unroll
    for (int rr = 0; rr < 8; rr++) {
        int row = wid * 8 + rr;
        const float* rp = sOut + row * LNW;
        float v[6];
        float sum = 0.f, sq2 = 0.f;
#pragma unroll
        for (int i = 0; i < 6; i++) {
            v[i] = rp[lane + i * 32];
            sum += v[i];
            sq2 += v[i] * v[i];
        }
#pragma unroll
        for (int o = 16; o > 0; o >>= 1) {
            sum += __shfl_xor_sync(0xffffffffu, sum, o);
            sq2 += __shfl_xor_sync(0xffffffffu, sq2, o);
        }
        float mean = sum * (1.f / C);
        float var  = sq2 * (1.f / C) - mean * mean;
        float rstd = rsqrtf(var + 1e-5f);

        int tok = win_row_to_tok(m0 + row);
        float* x1p = x1 + (size_t)tok * C;
        __nv_bfloat16* xnp = xn2 + (size_t)tok * C;
#pragma unroll
        for (int i = 0; i < 6; i++) {
            int c = lane + i * 32;
            x1p[c] = v[i];
            xnp[c] = __float2bfloat16((v[i] - mean) * rstd * sg[i] + bg[i]);
        }
    }
}

// ---------------- fused MLP v2: 128-row CTA, 512 threads -------------------
// out = gelu(xn2@W1+b1)@W2 + b2 + x1, hidden chunked 4 x 192 in smem.
// smem: sXn [0,49152) ; sH [49152,98304) ; sB 2x12288 [98304,122880)
#define MLP_SMEM 122880

__device__ __forceinline__ void mlp_gemm_inner(uint32_t aBase, uint32_t sbBase,
                                               const __nv_bfloat16* __restrict__ Wg,
                                               int rstride, int rowbase, int coloff,
                                               int wm, int wn, int tid, int lane,
                                               float acc[2][6][4]) {
    auto issueW = [&](int s, int buf) {
#pragma unroll
        for (int j = 0; j < 2; j++) {
            int i = tid + j * 512;
            if (i < 768) {
                int kl = i / 24, cch = i % 24;
                cpasync16(sbBase + buf * 12288 + kl * 384 + ((cch ^ (kl & 7)) << 4),
                          Wg + (size_t)(rowbase + s * 32 + kl) * rstride + coloff + cch * 8);
            }
        }
        asm volatile("cp.async.commit_group;" ::: "memory");
    };

    issueW(0, 0);
    for (int s = 0; s < 6; s++) {
        if (s < 5) {
            issueW(s + 1, (s + 1) & 1);
            asm volatile("cp.async.wait_group 1;" ::: "memory");
        } else {
            asm volatile("cp.async.wait_group 0;" ::: "memory");
        }
        __syncthreads();
        uint32_t bb = sbBase + (s & 1) * 12288;
#pragma unroll
        for (int t = 0; t < 2; t++) {
            int kk = s * 2 + t;
            uint32_t af[2][4];
#pragma unroll
            for (int fi = 0; fi < 2; fi++) {
                int row = wm + fi * 16 + (lane & 7) + 8 * ((lane >> 3) & 1);
                int ch  = 2 * kk + (lane >> 4);
                ldsm_x4(af[fi], aBase + row * 384 + ((ch ^ (row & 7)) << 4));
            }
            uint32_t bfr[6][2];
#pragma unroll
            for (int j = 0; j < 3; j++) {
                int kl = t * 16 + (lane & 7) + 8 * ((lane >> 3) & 1);
                int cn = (wn >> 3) + 2 * j + (lane >> 4);
                uint32_t t4[4];
                ldsm_x4_t(t4, bb + kl * 384 + ((cn ^ (kl & 7)) << 4));
                bfr[2 * j][0] = t4[0]; bfr[2 * j][1] = t4[1];
                bfr[2 * j + 1][0] = t4[2]; bfr[2 * j + 1][1] = t4[3];
            }
#pragma unroll
            for (int fi = 0; fi < 2; fi++)
#pragma unroll
                for (int nj = 0; nj < 6; nj++)
                    mma_bf16(acc[fi][nj], af[fi], bfr[nj]);
        }
        __syncthreads();
    }
}

__global__ __launch_bounds__(512) void mlp_kernel(const __nv_bfloat16* __restrict__ xn,
                                                  const __nv_bfloat16* __restrict__ w1,
                                                  const float* __restrict__ b1,
                                                  const __nv_bfloat16* __restrict__ w2,
                                                  const float* __restrict__ b2,
                                                  const float* __restrict__ x1,
                                                  float* __restrict__ out) {
    extern __shared__ char sm[];
    char* sH_p = sm + 49152;
    uint32_t sxn = smem_u32(sm);
    uint32_t shb = sxn + 49152;
    uint32_t sbb = sxn + 98304;

    int tid = threadIdx.x;
    int wid = tid >> 5, lane = tid & 31;
    int m0 = blockIdx.x * 128;
    int wm = (wid & 3) * 32;          // 4 M-groups x 32 rows
    int wn = (wid >> 2) * 48;         // 4 N-groups x 48 cols
    int g = lane >> 2, q2 = (lane & 3) * 2;

    // load xn tile: 128 rows x 24 chunks = 3072
#pragma unroll
    for (int j = 0; j < 6; j++) {
        int i = tid + j * 512;
        int r = i / 24, cch = i % 24;
        cpasync16(sxn + r * 384 + ((cch ^ (r & 7)) << 4), xn + (size_t)(m0 + r) * C + cch * 8);
    }
    asm volatile("cp.async.commit_group;" ::: "memory");
    asm volatile("cp.async.wait_group 0;" ::: "memory");
    __syncthreads();

    float acc2[2][6][4];
#pragma unroll
    for (int i = 0; i < 2; i++)
#pragma unroll
        for (int j = 0; j < 6; j++)
#pragma unroll
            for (int q = 0; q < 4; q++) acc2[i][j][q] = 0.f;

    for (int c = 0; c < 4; c++) {
        float acc1[2][6][4];
#pragma unroll
        for (int i = 0; i < 2; i++)
#pragma unroll
            for (int j = 0; j < 6; j++)
#pragma unroll
                for (int q = 0; q < 4; q++) acc1[i][j][q] = 0.f;
        mlp_gemm_inner(sxn, sbb, w1, 4 * C, 0, c * 192, wm, wn, tid, lane, acc1);

        const float is2 = 0.70710678118654752f;
#pragma unroll
        for (int fi = 0; fi < 2; fi++) {
            int rl = wm + fi * 16 + g;
            int rh = rl + 8;
#pragma unroll
            for (int nj = 0; nj < 6; nj++) {
                int colL = wn + nj * 8 + q2;
                int gcol = c * 192 + colL;
                float bi0 = b1[gcol], bi1 = b1[gcol + 1];
                float v00 = acc1[fi][nj][0] + bi0;
                float v01 = acc1[fi][nj][1] + bi1;
                float v10 = acc1[fi][nj][2] + bi0;
                float v11 = acc1[fi][nj][3] + bi1;
                v00 = 0.5f * v00 * (1.f + erff(v00 * is2));
                v01 = 0.5f * v01 * (1.f + erff(v01 * is2));
                v10 = 0.5f * v10 * (1.f + erff(v10 * is2));
                v11 = 0.5f * v11 * (1.f + erff(v11 * is2));
                int chh = colL >> 3;
                *(uint32_t*)(sH_p + rl * 384 + ((chh ^ (rl & 7)) << 4) + q2 * 2) = packbf(v00, v01);
                *(uint32_t*)(sH_p + rh * 384 + ((chh ^ (rh & 7)) << 4) + q2 * 2) = packbf(v10, v11);
            }
        }
        __syncthreads();

        mlp_gemm_inner(shb, sbb, w2, C, c * 192, 0, wm, wn, tid, lane, acc2);
    }

#pragma unroll
    for (int fi = 0; fi < 2; fi++) {
        int ml = m0 + wm + fi * 16 + g;
        int mh = ml + 8;
#pragma unroll
        for (int nj = 0; nj < 6; nj++) {
            int col = wn + nj * 8 + q2;
            float bi0 = b2[col], bi1 = b2[col + 1];
            float2 xl = *(const float2*)&x1[(size_t)ml * C + col];
            float2 xh = *(const float2*)&x1[(size_t)mh * C + col];
            *(float2*)&out[(size_t)ml * C + col] =
                make_float2(acc2[fi][nj][0] + bi0 + xl.x, acc2[fi][nj][1] + bi1 + xl.y);
            *(float2*)&out[(size_t)mh * C + col] =
                make_float2(acc2[fi][nj][2] + bi0 + xh.x, acc2[fi][nj][3] + bi1 + xh.y);
        }
    }
}

// ---------------- launch ---------------------------------------------------
extern "C" void kernel_launch(void* const* d_in, const int* in_sizes, int n_in,
                              void* d_out, int out_size) {
    const float* x      = (const float*)d_in[0];
    const float* qkv_w  = (const float*)d_in[1];
    const float* qkv_b  = (const float*)d_in[2];
    const float* proj_w = (const float*)d_in[3];
    const float* proj_b = (const float*)d_in[4];
    const float* rpb    = (const float*)d_in[5];
    const float* n1s    = (const float*)d_in[6];
    const float* n1b    = (const float*)d_in[7];
    const float* n2s    = (const float*)d_in[8];
    const float* n2b    = (const float*)d_in[9];
    const float* w1     = (const float*)d_in[10];
    const float* b1     = (const float*)d_in[11];
    const float* w2     = (const float*)d_in[12];
    const float* b2     = (const float*)d_in[13];
    float* out = (float*)d_out;

    __nv_bfloat16 *xw, *qkv, *xn2, *wqkv, *wproj, *ww1, *ww2;
    float *x1, *abias;
    cudaGetSymbolAddress((void**)&xw,    g_xw);
    cudaGetSymbolAddress((void**)&qkv,   g_qkv);
    cudaGetSymbolAddress((void**)&x1,    g_x1);
    cudaGetSymbolAddress((void**)&xn2,   g_xn2);
    cudaGetSymbolAddress((void**)&wqkv,  g_wqkv);
    cudaGetSymbolAddress((void**)&wproj, g_wproj);
    cudaGetSymbolAddress((void**)&ww1,   g_w1);
    cudaGetSymbolAddress((void**)&ww2,   g_w2);
    cudaGetSymbolAddress((void**)&abias, g_abias);

    cudaFuncSetAttribute(attnproj_kernel, cudaFuncAttributeMaxDynamicSharedMemorySize, MK_SMEM);
    cudaFuncSetAttribute(mlp_kernel,      cudaFuncAttributeMaxDynamicSharedMemorySize, MLP_SMEM);

    // prep (2 launches)
    prep_w_kernel<<<(SZ_ALL + 255) / 256, 256>>>(qkv_w, proj_w, w1, w2,
                                                 wqkv, wproj, ww1, ww2);
    abias_kernel<<<(NH * 64 * 64 + 255) / 256, 256>>>(rpb, abias);

    // 1. LN1 + shift + window gather -> bf16
    ln_kernel<<<NTOK / 8, 256>>>(x, n1s, n1b, xw);

    // 2. QKV GEMM -> bf16
    qkv_gemm<<<dim3((3 * C) / GBN, NTOK / GBM), 256>>>(xw, wqkv, qkv_b, qkv,
                                                       NTOK, 3 * C, C);

    // 3. attention + proj + residual + LN2 -> x1 (fp32) & xn2 (bf16)
    attnproj_kernel<<<NTOK / 128, 512, MK_SMEM>>>(qkv, abias, wproj, proj_b,
                                                  x, n2s, n2b, x1, xn2);

    // 4. fused MLP + residual -> out
    mlp_kernel<<<NTOK / 128, 512, MLP_SMEM>>>(xn2, ww1, b1, ww2, b2, x1, out);
}